// round 7
// baseline (speedup 1.0000x reference)
#include <cuda_runtime.h>
#include <cuda_bf16.h>
#include <math.h>
#include <stdint.h>

typedef unsigned long long ull;

#define CD 1024
#define LD 80
#define WDIM 300
#define HW 196
#define BT 4
#define NP 784
#define OD 2048
#define NE (BT*LD*CD)

#define MODE_NONE 0
#define MODE_ZRH  1
#define MODE_GRU2 2
#define MODE_TANH 3

// tensor-GEMM tile config
#define TM 128
#define TN 64
#define TK 64                  // staged k-chunk; bf16 row = 128 bytes = SW128 atom

#define SMEM_SWIZZLE_128B(byte_offset) ((byte_offset) ^ (((byte_offset) >> 3) & 0x70))

// ---------------- scratch ----------------
__device__ float d_fwd[LD*CD];
__device__ float d_v[CD];
__device__ float d_c0s[1];
__device__ float d_ball[3*CD];
__device__ float d_wall[3*CD*CD];
__device__ float d_fwh[NP*CD];
__device__ float d_coeff[NP*LD];
__device__ float d_g[NE];
__device__ float d_nodes[NE];
__device__ float d_abuf[NE];
__device__ float d_zrh[BT*LD*3*CD];

// ---------------- helpers ----------------
__device__ __forceinline__ uint32_t smem_to_u32(const void* p) {
    uint32_t a;
    asm("{ .reg .u64 t; cvta.to.shared.u64 t, %1; cvt.u32.u64 %0, t; }" : "=r"(a) : "l"(p));
    return a;
}
__device__ __forceinline__ void sts128(uint32_t addr, uint32_t r0, uint32_t r1,
                                       uint32_t r2, uint32_t r3) {
    asm volatile("st.shared.v4.b32 [%0], {%1, %2, %3, %4};"
        :: "r"(addr), "r"(r0), "r"(r1), "r"(r2), "r"(r3) : "memory");
}
__device__ __forceinline__ uint32_t pkbf(__nv_bfloat16 a, __nv_bfloat16 b) {
    return (uint32_t)__bfloat16_as_ushort(a) | ((uint32_t)__bfloat16_as_ushort(b) << 16);
}
__device__ __forceinline__ void ldsm_x4(uint32_t* r, uint32_t addr) {
    asm volatile("ldmatrix.sync.aligned.m8n8.x4.shared.b16 {%0,%1,%2,%3}, [%4];"
        : "=r"(r[0]), "=r"(r[1]), "=r"(r[2]), "=r"(r[3]) : "r"(addr));
}
__device__ __forceinline__ void mma16816(float* c, const uint32_t* a, const uint32_t* b) {
    asm volatile("mma.sync.aligned.m16n8k16.row.col.f32.bf16.bf16.f32 "
        "{%0,%1,%2,%3}, {%4,%5,%6,%7}, {%8,%9}, {%0,%1,%2,%3};"
        : "+f"(c[0]), "+f"(c[1]), "+f"(c[2]), "+f"(c[3])
        : "r"(a[0]), "r"(a[1]), "r"(a[2]), "r"(a[3]), "r"(b[0]), "r"(b[1]));
}

// ---------------- prep kernels ----------------
__global__ void k_wsum(const float* __restrict__ w3, const float* __restrict__ w4,
                       const float* __restrict__ w5) {
    const int T = CD*CD;
    int stride = gridDim.x * blockDim.x;
    for (int i = blockIdx.x*blockDim.x + threadIdx.x; i < 3*T; i += stride) {
        int which = i / T;
        int rem = i - which*T;
        int r = rem >> 10, c = rem & (CD-1);
        const float* w = (which==0) ? w3 : (which==1) ? w4 : w5;
        d_wall[i] = w[r*2*CD + c] + w[r*2*CD + CD + c];
    }
}

__global__ void k_bias(const float* __restrict__ b3, const float* __restrict__ u3b,
                       const float* __restrict__ b4, const float* __restrict__ b5,
                       const float* __restrict__ u5b) {
    int i = blockIdx.x*256 + threadIdx.x;
    if (i < CD) {
        d_ball[i]        = b3[i] + u3b[i];
        d_ball[CD + i]   = b4[i] + u3b[i];   // torch bug kept: r-gate reuses fc_eq3_u
        d_ball[2*CD + i] = b5[i] + u5b[i];
    }
}

__global__ void k_v(const float* __restrict__ fc3_w, const float* __restrict__ fca_w) {
    __shared__ float fs[CD];
    for (int j = threadIdx.x; j < CD; j += 256) fs[j] = fca_w[j];
    __syncthreads();
    int i = blockIdx.x*256 + threadIdx.x;
    float acc = 0.f;
    #pragma unroll 8
    for (int j = 0; j < CD; ++j) acc += fs[j] * fc3_w[j*CD + i];
    d_v[i] = acc;
}

__global__ void k_c0(const float* __restrict__ fc3_b, const float* __restrict__ fca_w,
                     const float* __restrict__ fca_b) {
    __shared__ float red[8];
    float acc = 0.f;
    for (int j = threadIdx.x; j < CD; j += 256) acc += fc3_b[j] * fca_w[j];
    #pragma unroll
    for (int o = 16; o > 0; o >>= 1) acc += __shfl_xor_sync(0xffffffffu, acc, o);
    if ((threadIdx.x & 31) == 0) red[threadIdx.x >> 5] = acc;
    __syncthreads();
    if (threadIdx.x == 0) {
        float s = 0.f;
        #pragma unroll
        for (int q = 0; q < 8; ++q) s += red[q];
        d_c0s[0] = s + fca_b[0];
    }
}

// ---------------- staging: fp32 -> split bf16 hi/lo, SW128 swizzled ----------------
__device__ __forceinline__ void stage_tile(
    uint32_t hi_addr, uint32_t lo_addr,
    const float* __restrict__ src, int ld,
    int row0, int rowmask, int row_limit,
    int k0, int K, int nrows, int tid)
{
    int nch = nrows * 8;                 // 8-elem chunks (16 bytes of bf16)
    for (int c = tid; c < nch; c += 128) {
        int row = c >> 3;
        int col8 = (c & 7) * 8;
        int gr = row0 + row;
        bool rok = gr < row_limit;
        int er = gr & rowmask;
        float v[8];
        const float* p = src + (size_t)er*ld + k0 + col8;
        if (rok && (k0 + col8 + 8 <= K)) {
            float4 x = *(const float4*)p;
            float4 y = *(const float4*)(p + 4);
            v[0]=x.x; v[1]=x.y; v[2]=x.z; v[3]=x.w;
            v[4]=y.x; v[5]=y.y; v[6]=y.z; v[7]=y.w;
        } else {
            #pragma unroll
            for (int j = 0; j < 8; ++j) {
                int k = k0 + col8 + j;
                v[j] = (rok && k < K) ? p[j] : 0.f;
            }
        }
        uint32_t hw[4], lw[4];
        #pragma unroll
        for (int j = 0; j < 4; ++j) {
            __nv_bfloat16 h0 = __float2bfloat16(v[2*j]);
            __nv_bfloat16 h1 = __float2bfloat16(v[2*j+1]);
            __nv_bfloat16 l0 = __float2bfloat16(v[2*j]   - __bfloat162float(h0));
            __nv_bfloat16 l1 = __float2bfloat16(v[2*j+1] - __bfloat162float(h1));
            hw[j] = pkbf(h0, h1);
            lw[j] = pkbf(l0, l1);
        }
        uint32_t off = SMEM_SWIZZLE_128B((uint32_t)(row*128 + col8*2));
        sts128(hi_addr + off, hw[0], hw[1], hw[2], hw[3]);
        sts128(lo_addr + off, lw[0], lw[1], lw[2], lw[3]);
    }
}

// ---------------- tensor-core GEMM via mma.sync (HMMA path, compute_103-safe) --------
// C = epi( A@B^T [+ A2@B2^T] + bias ), fp32 emulated as bf16 hi*hi + hi*lo + lo*hi.
// Static 48KB shared: A hi/lo (2x16K) + B hi/lo (2x8K) = 49152 bytes exactly.
template<int MODE>
__global__ __launch_bounds__(128) void t_gemm(
    const float* __restrict__ A, int lda,
    const float* __restrict__ B, int ldb,
    const float* __restrict__ A2, int lda2,
    const float* __restrict__ B2, int ldb2,
    int b2mask, int n2_limit,
    int M, int N, int K,
    const float* __restrict__ bias,
    const float* __restrict__ aux1,
    float* __restrict__ aux2,
    float* __restrict__ C, int ldc)
{
    __shared__ __align__(128) char dsm[49152];
    uint32_t base = smem_to_u32(dsm);
    uint32_t a_hi = base;
    uint32_t a_lo = base + 16384;
    uint32_t b_hi = base + 32768;
    uint32_t b_lo = base + 40960;

    const int tid = threadIdx.x;
    const int wid = tid >> 5;
    const int lane = tid & 31;
    const int m0 = blockIdx.y * TM;
    const int n0 = blockIdx.x * TN;
    const int wrow = wid * 32;           // warp's 32-row slice of the tile

    // ldmatrix lane addressing (x4: four 8x8 mats; q selects mat)
    const int q = lane >> 3, rr = lane & 7;
    const int lrow = (q & 1) * 8 + rr;   // row within 16-row tile
    const int lkof = (q >> 1) * 8;       // k offset within 16

    float acc[2][8][4];
    #pragma unroll
    for (int i = 0; i < 2; ++i)
        #pragma unroll
        for (int j = 0; j < 8; ++j)
            #pragma unroll
            for (int s = 0; s < 4; ++s) acc[i][j][s] = 0.f;

    const int ntiles1 = (K + TK - 1) / TK;
    const bool do2 = (A2 != nullptr) && (n0 < n2_limit);
    const int ntiles = do2 ? 2*ntiles1 : ntiles1;
    const int NOMASKI = 0x7FFFFFFF;

    for (int t = 0; t < ntiles; ++t) {
        int pass = (t >= ntiles1) ? 1 : 0;
        int k0c = (t - pass*ntiles1) * TK;
        const float* Ap = pass ? A2 : A;
        const float* Bp = pass ? B2 : B;
        int la = pass ? lda2 : lda;
        int lb = pass ? ldb2 : ldb;
        int bm = pass ? b2mask : NOMASKI;

        stage_tile(a_hi, a_lo, Ap, la, m0, NOMASKI, M, k0c, K, TM, tid);
        stage_tile(b_hi, b_lo, Bp, lb, n0, bm,      N, k0c, K, TN, tid);
        __syncthreads();

        #pragma unroll
        for (int k0 = 0; k0 < TK; k0 += 16) {
            uint32_t ah[2][4], al[2][4];
            #pragma unroll
            for (int i = 0; i < 2; ++i) {
                uint32_t off = SMEM_SWIZZLE_128B(
                    (uint32_t)((wrow + i*16 + lrow)*128 + (k0 + lkof)*2));
                ldsm_x4(ah[i], a_hi + off);
                ldsm_x4(al[i], a_lo + off);
            }
            uint32_t bh[8][2], bl[8][2];
            #pragma unroll
            for (int j = 0; j < 4; ++j) {
                uint32_t off = SMEM_SWIZZLE_128B(
                    (uint32_t)((j*16 + lrow)*128 + (k0 + lkof)*2));
                uint32_t r[4];
                ldsm_x4(r, b_hi + off);
                bh[2*j][0] = r[0]; bh[2*j][1] = r[2];
                bh[2*j+1][0] = r[1]; bh[2*j+1][1] = r[3];
                ldsm_x4(r, b_lo + off);
                bl[2*j][0] = r[0]; bl[2*j][1] = r[2];
                bl[2*j+1][0] = r[1]; bl[2*j+1][1] = r[3];
            }
            #pragma unroll
            for (int i = 0; i < 2; ++i)
                #pragma unroll
                for (int j = 0; j < 8; ++j) {
                    mma16816(acc[i][j], ah[i], bh[j]);   // hi*hi
                    mma16816(acc[i][j], ah[i], bl[j]);   // hi*lo
                    mma16816(acc[i][j], al[i], bh[j]);   // lo*hi
                }
        }
        __syncthreads();
    }

    // epilogue: C fragment m16n8 — rows g, g+8; cols 2t, 2t+1
    const int g = lane >> 2, tq = (lane & 3)*2;
    #pragma unroll
    for (int i = 0; i < 2; ++i) {
        #pragma unroll
        for (int half = 0; half < 2; ++half) {
            int m = m0 + wrow + i*16 + g + half*8;
            if (m >= M) continue;
            #pragma unroll
            for (int j = 0; j < 8; ++j) {
                #pragma unroll
                for (int s = 0; s < 2; ++s) {
                    int n = n0 + j*8 + tq + s;
                    if (n >= N) continue;
                    float x = acc[i][j][half*2 + s];
                    size_t idx = (size_t)m*ldc + n;
                    if (MODE == MODE_NONE) {
                        C[idx] = x;
                    } else if (MODE == MODE_ZRH) {
                        x += bias[n];
                        float y;
                        if (n < CD)        y = 1.f/(1.f + expf(-x));
                        else if (n < 2*CD) y = (1.f/(1.f + expf(-x))) * aux1[m*CD + (n-CD)];
                        else               y = x;
                        C[idx] = y;
                    } else if (MODE == MODE_GRU2) {
                        float ht   = aux1[m*3072 + 2048 + n];
                        float z    = aux1[m*3072 + n];
                        float prev = aux2[m*CD + n];
                        C[idx] = (1.f - z)*prev + z*tanhf(x + ht);
                    } else { // MODE_TANH
                        x += bias[n];
                        C[idx] = tanhf(x);
                    }
                }
            }
        }
    }
}

// ---------------- semantic-branch kernels ----------------
__global__ __launch_bounds__(256) void k_coeff() {
    __shared__ float fwh_s[CD];
    __shared__ float v_s[CD];
    int n = blockIdx.x;
    for (int i = threadIdx.x; i < CD; i += 256) {
        fwh_s[i] = d_fwh[n*CD + i];
        v_s[i]   = d_v[i];
    }
    __syncthreads();
    int warp = threadIdx.x >> 5, lane = threadIdx.x & 31;
    float c0 = d_c0s[0];
    for (int l = warp; l < LD; l += 8) {
        const float* fw = d_fwd + l*CD;
        float acc = 0.f;
        #pragma unroll 8
        for (int i = lane; i < CD; i += 32) {
            float p = fwh_s[i] * fw[i];
            float tv;
            asm("tanh.approx.f32 %0, %1;" : "=f"(tv) : "f"(p));
            acc += tv * v_s[i];
        }
        #pragma unroll
        for (int o = 16; o > 0; o >>= 1) acc += __shfl_xor_sync(0xffffffffu, acc, o);
        if (lane == 0) d_coeff[n*LD + l] = acc + c0;
    }
}

__global__ __launch_bounds__(256) void k_softmax() {
    int g = blockIdx.x*8 + (threadIdx.x >> 5);
    int lane = threadIdx.x & 31;
    if (g >= NP*LD/HW) return;
    float* p = d_coeff + g*HW;
    float vals[7];
    float mx = -1e30f;
    #pragma unroll
    for (int q = 0; q < 7; ++q) {
        int i = lane + q*32;
        vals[q] = (i < HW) ? p[i] : -1e30f;
        mx = fmaxf(mx, vals[q]);
    }
    #pragma unroll
    for (int o = 16; o > 0; o >>= 1) mx = fmaxf(mx, __shfl_xor_sync(0xffffffffu, mx, o));
    float s = 0.f;
    #pragma unroll
    for (int q = 0; q < 7; ++q) {
        int i = lane + q*32;
        if (i < HW) { vals[q] = expf(vals[q] - mx); s += vals[q]; }
    }
    #pragma unroll
    for (int o = 16; o > 0; o >>= 1) s += __shfl_xor_sync(0xffffffffu, s, o);
    float inv = 1.f / s;
    #pragma unroll
    for (int q = 0; q < 7; ++q) {
        int i = lane + q*32;
        if (i < HW) p[i] = vals[q]*inv;
    }
}

__global__ __launch_bounds__(256) void k_g(const float* __restrict__ img) {
    __shared__ float s[HW];
    int b = blockIdx.x / LD, l = blockIdx.x % LD;
    for (int tt = threadIdx.x; tt < HW; tt += 256)
        s[tt] = d_coeff[(b*HW + tt)*LD + l];
    __syncthreads();
    const float* xb = img + b*HW*CD;
    int c = threadIdx.x;
    float a0 = 0.f, a1 = 0.f, a2 = 0.f, a3 = 0.f;
    #pragma unroll 4
    for (int tt = 0; tt < HW; ++tt) {
        float w = s[tt];
        const float* xr = xb + tt*CD;
        a0 += w*xr[c]; a1 += w*xr[c+256]; a2 += w*xr[c+512]; a3 += w*xr[c+768];
    }
    float* go = d_g + (b*LD + l)*CD;
    float* no = d_nodes + (b*LD + l)*CD;
    go[c] = a0; go[c+256] = a1; go[c+512] = a2; go[c+768] = a3;
    no[c] = a0; no[c+256] = a1; no[c+512] = a2; no[c+768] = a3;
}

__global__ __launch_bounds__(256) void k_a(const float* __restrict__ adj) {
    __shared__ float ar[LD];
    int b = blockIdx.x / LD, nn = blockIdx.x % LD;
    if (threadIdx.x < LD) ar[threadIdx.x] = adj[nn*LD + threadIdx.x];
    __syncthreads();
    int c = threadIdx.x;
    const float* nb = d_nodes + b*LD*CD;
    float a0 = 0.f, a1 = 0.f, a2 = 0.f, a3 = 0.f;
    #pragma unroll 4
    for (int m = 0; m < LD; ++m) {
        float w = ar[m];
        const float* nr = nb + m*CD;
        a0 += w*nr[c]; a1 += w*nr[c+256]; a2 += w*nr[c+512]; a3 += w*nr[c+768];
    }
    float* ao = d_abuf + (b*LD + nn)*CD;
    ao[c] = a0; ao[c+256] = a1; ao[c+512] = a2; ao[c+768] = a3;
}

// ---------------- host ----------------
template<int MODE>
static void tg(const float* A, int lda, const float* B, int ldb,
               const float* A2, int lda2, const float* B2, int ldb2,
               int b2mask, int n2_limit,
               int M, int N, int K,
               const float* bias, const float* aux1, float* aux2,
               float* C, int ldc) {
    dim3 grid((N + TN - 1)/TN, (M + TM - 1)/TM);
    t_gemm<MODE><<<grid, 128>>>(A, lda, B, ldb, A2, lda2, B2, ldb2,
                                b2mask, n2_limit, M, N, K,
                                bias, aux1, aux2, C, ldc);
}

extern "C" void kernel_launch(void* const* d_in, const int* in_sizes, int n_in,
                              void* d_out, int out_size) {
    const float* img  = (const float*)d_in[0];
    const float* wemb = (const float*)d_in[1];
    const float* adj  = (const float*)d_in[2];
    const float* fc1  = (const float*)d_in[3];
    const float* fc2  = (const float*)d_in[4];
    const float* fc3  = (const float*)d_in[5];
    const float* fc3b = (const float*)d_in[6];
    const float* fca  = (const float*)d_in[7];
    const float* fcab = (const float*)d_in[8];
    const float* w3   = (const float*)d_in[9];
    const float* b3   = (const float*)d_in[10];
    const float* u3   = (const float*)d_in[11];
    const float* u3b  = (const float*)d_in[12];
    const float* w4   = (const float*)d_in[13];
    const float* b4   = (const float*)d_in[14];
    const float* w5   = (const float*)d_in[15];
    const float* b5   = (const float*)d_in[16];
    const float* u5   = (const float*)d_in[17];
    const float* u5b  = (const float*)d_in[18];
    const float* fco  = (const float*)d_in[19];
    const float* fcob = (const float*)d_in[20];
    float* out = (float*)d_out;

    float *p_fwd, *p_wall, *p_ball, *p_fwh, *p_g, *p_nodes, *p_a, *p_zrh;
    cudaGetSymbolAddress((void**)&p_fwd,   d_fwd);
    cudaGetSymbolAddress((void**)&p_wall,  d_wall);
    cudaGetSymbolAddress((void**)&p_ball,  d_ball);
    cudaGetSymbolAddress((void**)&p_fwh,   d_fwh);
    cudaGetSymbolAddress((void**)&p_g,     d_g);
    cudaGetSymbolAddress((void**)&p_nodes, d_nodes);
    cudaGetSymbolAddress((void**)&p_a,     d_abuf);
    cudaGetSymbolAddress((void**)&p_zrh,   d_zrh);

    const int NOMASK = 0x7FFFFFFF;

    // weight prep
    k_wsum<<<3072, 256>>>(w3, w4, w5);
    k_bias<<<4, 256>>>(b3, u3b, b4, b5, u5b);
    k_v<<<4, 256>>>(fc3, fca);
    k_c0<<<1, 256>>>(fc3b, fca, fcab);

    // semantic branch
    tg<MODE_NONE>(wemb, WDIM, fc2, WDIM, nullptr, 0, nullptr, 0, NOMASK, 0,
                  LD, CD, WDIM, nullptr, nullptr, nullptr, p_fwd, CD);
    tg<MODE_NONE>(img, CD, fc1, CD, nullptr, 0, nullptr, 0, NOMASK, 0,
                  NP, CD, CD, nullptr, nullptr, nullptr, p_fwh, CD);
    k_coeff<<<NP, 256>>>();
    k_softmax<<<40, 256>>>();
    k_g<<<BT*LD, 256>>>(img);   // also seeds nodes = g

    // GGNN: per step, fused ZRH GEMM (N=3072, dual-K with u3 replay) + GRU update GEMM
    for (int step = 0; step < 3; ++step) {
        k_a<<<BT*LD, 256>>>(adj);
        tg<MODE_ZRH>(p_a, CD, p_wall, CD, p_nodes, CD, u3, CD, CD-1, 2*CD,
                     BT*LD, 3*CD, CD, p_ball, p_nodes, nullptr, p_zrh, 3*CD);
        tg<MODE_GRU2>(p_zrh + CD, 3*CD, u5, CD, nullptr, 0, nullptr, 0, NOMASK, 0,
                      BT*LD, CD, CD, nullptr, p_zrh, p_nodes, p_nodes, CD);
    }

    // out = tanh([nodes, g] @ fco^T + fco_b) — dual-K over fco column halves
    tg<MODE_TANH>(p_nodes, CD, fco, OD, p_g, CD, fco + CD, OD, NOMASK, 0x7FFFFFFF,
                  BT*LD, OD, CD, fcob, nullptr, nullptr, out, OD);
}

// round 8
// speedup vs baseline: 2.2283x; 2.2283x over previous
#include <cuda_runtime.h>
#include <cuda_bf16.h>
#include <math.h>
#include <stdint.h>

#define CD 1024
#define LD 80
#define WDIM 300
#define WPAD 320
#define HW 196
#define BT 4
#define NP 784
#define OD 2048
#define NR (BT*LD)
#define NE (NR*CD)

#define MODE_NONE 0
#define MODE_ZRH  1
#define MODE_GRU2 2
#define MODE_TANH 3

#define TM 128
#define TN 64
#define NOMASK 0x7FFFFFFF

// ---------------- fp32 scratch ----------------
__device__ float d_fwd[LD*CD];
__device__ float d_v[CD];
__device__ float d_c0s[1];
__device__ float d_ball[3*CD];
__device__ float d_fwh[NP*CD];
__device__ float d_coeff[NP*LD];
__device__ float d_nodes[NE];
__device__ float d_zbuf[NE];
__device__ float d_hbuf[NE];

// ---------------- bf16 hi/lo operand buffers ----------------
__device__ unsigned short c_img_h[NP*CD],    c_img_l[NP*CD];
__device__ unsigned short c_fc1_h[CD*CD],    c_fc1_l[CD*CD];
__device__ unsigned short c_wemb_h[LD*WPAD], c_wemb_l[LD*WPAD];
__device__ unsigned short c_fc2_h[CD*WPAD],  c_fc2_l[CD*WPAD];
__device__ unsigned short c_wall_h[3*CD*CD], c_wall_l[3*CD*CD];
__device__ unsigned short c_u3_h[CD*CD],     c_u3_l[CD*CD];
__device__ unsigned short c_u5_h[CD*CD],     c_u5_l[CD*CD];
__device__ unsigned short c_fco_h[OD*2*CD],  c_fco_l[OD*2*CD];
__device__ unsigned short c_nodes_h[NE],     c_nodes_l[NE];
__device__ unsigned short c_a_h[NE],         c_a_l[NE];
__device__ unsigned short c_rn_h[NE],        c_rn_l[NE];
__device__ unsigned short c_g_h[NE],         c_g_l[NE];

// ---------------- helpers ----------------
__device__ __forceinline__ uint32_t smem_to_u32(const void* p) {
    uint32_t a;
    asm("{ .reg .u64 t; cvta.to.shared.u64 t, %1; cvt.u32.u64 %0, t; }" : "=r"(a) : "l"(p));
    return a;
}
__device__ __forceinline__ void split_bf(float v, unsigned short* h, unsigned short* l) {
    __nv_bfloat16 hb = __float2bfloat16(v);
    *h = __bfloat16_as_ushort(hb);
    *l = __bfloat16_as_ushort(__float2bfloat16(v - __bfloat162float(hb)));
}
__device__ __forceinline__ void ldsm_x4(uint32_t* r, uint32_t addr) {
    asm volatile("ldmatrix.sync.aligned.m8n8.x4.shared.b16 {%0,%1,%2,%3}, [%4];"
        : "=r"(r[0]), "=r"(r[1]), "=r"(r[2]), "=r"(r[3]) : "r"(addr));
}
__device__ __forceinline__ void mma16816(float* c, const uint32_t* a, const uint32_t* b) {
    asm volatile("mma.sync.aligned.m16n8k16.row.col.f32.bf16.bf16.f32 "
        "{%0,%1,%2,%3}, {%4,%5,%6,%7}, {%8,%9}, {%0,%1,%2,%3};"
        : "+f"(c[0]), "+f"(c[1]), "+f"(c[2]), "+f"(c[3])
        : "r"(a[0]), "r"(a[1]), "r"(a[2]), "r"(a[3]), "r"(b[0]), "r"(b[1]));
}
__device__ __forceinline__ void cpasync16(uint32_t dst, const void* src, bool ok) {
    asm volatile("cp.async.cg.shared.global [%0], [%1], 16, %2;"
        :: "r"(dst), "l"(src), "r"(ok ? 16 : 0) : "memory");
}
__device__ __forceinline__ void cp_commit() {
    asm volatile("cp.async.commit_group;" ::: "memory");
}
__device__ __forceinline__ void cp_wait1() {
    asm volatile("cp.async.wait_group 1;" ::: "memory");
}
__device__ __forceinline__ void cp_wait0() {
    asm volatile("cp.async.wait_group 0;" ::: "memory");
}
__device__ __forceinline__ uint32_t sw64(uint32_t off) {
    return off ^ ((off >> 3) & 0x30);
}

// ---------------- conversion kernels ----------------
__global__ void k_conv(const float* __restrict__ src, unsigned short* __restrict__ hi,
                       unsigned short* __restrict__ lo, int R, int Ksrc, int ldp) {
    int stride = gridDim.x*blockDim.x;
    int total = R*ldp;
    if (Ksrc == ldp) {
        for (int i = blockIdx.x*blockDim.x + threadIdx.x; i < total; i += stride)
            split_bf(src[i], &hi[i], &lo[i]);
    } else {
        for (int i = blockIdx.x*blockDim.x + threadIdx.x; i < total; i += stride) {
            int r = i / ldp, c = i - r*ldp;
            float v = (c < Ksrc) ? src[r*Ksrc + c] : 0.f;
            split_bf(v, &hi[i], &lo[i]);
        }
    }
}

__global__ void k_wsum(const float* __restrict__ w3, const float* __restrict__ w4,
                       const float* __restrict__ w5) {
    const int T = CD*CD;
    int stride = gridDim.x * blockDim.x;
    for (int i = blockIdx.x*blockDim.x + threadIdx.x; i < 3*T; i += stride) {
        int which = i / T;
        int rem = i - which*T;
        int r = rem >> 10, c = rem & (CD-1);
        const float* w = (which==0) ? w3 : (which==1) ? w4 : w5;
        float val = w[r*2*CD + c] + w[r*2*CD + CD + c];
        split_bf(val, &c_wall_h[i], &c_wall_l[i]);
    }
}

__global__ void k_bias(const float* __restrict__ b3, const float* __restrict__ u3b,
                       const float* __restrict__ b4, const float* __restrict__ b5,
                       const float* __restrict__ u5b) {
    int i = blockIdx.x*256 + threadIdx.x;
    if (i < CD) {
        d_ball[i]        = b3[i] + u3b[i];
        d_ball[CD + i]   = b4[i] + u3b[i];   // torch bug kept: r-gate reuses fc_eq3_u
        d_ball[2*CD + i] = b5[i] + u5b[i];
    }
}

__global__ void k_v(const float* __restrict__ fc3_w, const float* __restrict__ fca_w) {
    __shared__ float fs[CD];
    for (int j = threadIdx.x; j < CD; j += 256) fs[j] = fca_w[j];
    __syncthreads();
    int i = blockIdx.x*256 + threadIdx.x;
    float acc = 0.f;
    #pragma unroll 8
    for (int j = 0; j < CD; ++j) acc += fs[j] * fc3_w[j*CD + i];
    d_v[i] = acc;
}

__global__ void k_c0(const float* __restrict__ fc3_b, const float* __restrict__ fca_w,
                     const float* __restrict__ fca_b) {
    __shared__ float red[8];
    float acc = 0.f;
    for (int j = threadIdx.x; j < CD; j += 256) acc += fc3_b[j] * fca_w[j];
    #pragma unroll
    for (int o = 16; o > 0; o >>= 1) acc += __shfl_xor_sync(0xffffffffu, acc, o);
    if ((threadIdx.x & 31) == 0) red[threadIdx.x >> 5] = acc;
    __syncthreads();
    if (threadIdx.x == 0) {
        float s = 0.f;
        #pragma unroll
        for (int q = 0; q < 8; ++q) s += red[q];
        d_c0s[0] = s + fca_b[0];
    }
}

// ---------------- tensor GEMM: cp.async double-buffered, pre-split bf16 operands ------
// C = epi( A@B^T [+ A2@B2^T] + bias ); fp32 via 3-term bf16 split (hh + hl + lh).
// smem: 2 stages x (A hi 8K | A lo 8K | B hi 4K | B lo 4K) = 49152 B static.
template<int MODE>
__global__ __launch_bounds__(256) void t_gemm(
    const unsigned short* __restrict__ Ah, const unsigned short* __restrict__ Al, int lda,
    const unsigned short* __restrict__ Bh, const unsigned short* __restrict__ Bl, int ldb,
    const unsigned short* __restrict__ A2h, const unsigned short* __restrict__ A2l, int lda2,
    const unsigned short* __restrict__ B2h, const unsigned short* __restrict__ B2l, int ldb2,
    int b2mask, int n2_limit,
    int M, int N, int Kpad,
    const float* __restrict__ bias,
    float* __restrict__ p0, float* __restrict__ p1, float* __restrict__ p2,
    unsigned short* __restrict__ q0, unsigned short* __restrict__ q1,
    float* __restrict__ C, int ldc)
{
    __shared__ __align__(128) char dsm[49152];
    uint32_t sbase = smem_to_u32(dsm);

    const int tid = threadIdx.x;
    const int wid = tid >> 5;
    const int lane = tid & 31;
    const int m0 = blockIdx.y * TM;
    const int n0 = blockIdx.x * TN;
    const int wm = (wid >> 1) * 32;
    const int wn = (wid & 1) * 32;

    const int qm = lane >> 3, rr = lane & 7;
    const int lrow = (qm & 1)*8 + rr;
    const int lkof = (qm >> 1)*8;

    float acc[2][4][4];
    #pragma unroll
    for (int i = 0; i < 2; ++i)
        #pragma unroll
        for (int j = 0; j < 4; ++j)
            #pragma unroll
            for (int s = 0; s < 4; ++s) acc[i][j][s] = 0.f;

    const int nst1 = Kpad >> 5;
    const bool do2 = (A2h != nullptr) && (n0 < n2_limit);
    const int nst = do2 ? 2*nst1 : nst1;

    // stage issuer: 6 cp.async per thread
    auto stage = [&](int t) {
        int pass = (t >= nst1) ? 1 : 0;
        int k0 = (t - pass*nst1) << 5;
        const unsigned short* pAh = pass ? A2h : Ah;
        const unsigned short* pAl = pass ? A2l : Al;
        const unsigned short* pBh = pass ? B2h : Bh;
        const unsigned short* pBl = pass ? B2l : Bl;
        int la = pass ? lda2 : lda;
        int lb = pass ? ldb2 : ldb;
        int bm = pass ? b2mask : NOMASK;
        uint32_t sb = sbase + (t & 1) * 24576;
        #pragma unroll
        for (int qq = 0; qq < 6; ++qq) {
            int c = tid + (qq << 8);
            if (qq < 4) {              // A: 1024 copies (hi 0-511, lo 512-1023)
                int row = (c & 511) >> 2;
                int quad = c & 3;
                int gr = m0 + row;
                bool ok = gr < M;
                const unsigned short* s = ((c < 512) ? pAh : pAl)
                                          + (size_t)(ok ? gr : 0)*la + k0 + quad*8;
                uint32_t off = sw64((uint32_t)(row*64 + quad*16));
                cpasync16(sb + ((c < 512) ? 0 : 8192) + off, s, ok);
            } else {                   // B: 512 copies (hi, lo)
                int cb = c - 1024;
                int row = (cb & 255) >> 2;
                int quad = cb & 3;
                int gn = n0 + row;
                bool ok = gn < N;
                int er = (ok ? gn : 0) & bm;
                const unsigned short* s = ((cb < 256) ? pBh : pBl)
                                          + (size_t)er*lb + k0 + quad*8;
                uint32_t off = sw64((uint32_t)(row*64 + quad*16));
                cpasync16(sb + 16384 + ((cb < 256) ? 0 : 4096) + off, s, ok);
            }
        }
        cp_commit();
    };

    stage(0);
    for (int t = 0; t < nst; ++t) {
        if (t + 1 < nst) { stage(t + 1); cp_wait1(); }
        else             { cp_wait0(); }
        __syncthreads();
        uint32_t sb = sbase + (t & 1) * 24576;
        uint32_t sa_hi = sb, sa_lo = sb + 8192, sb_hi = sb + 16384, sb_lo = sb + 20480;
        #pragma unroll
        for (int k0 = 0; k0 < 32; k0 += 16) {
            uint32_t ah[2][4], al[2][4], bh[4][2], bl[4][2];
            #pragma unroll
            for (int i = 0; i < 2; ++i) {
                uint32_t off = sw64((uint32_t)((wm + i*16 + lrow)*64 + (k0 + lkof)*2));
                ldsm_x4(ah[i], sa_hi + off);
                ldsm_x4(al[i], sa_lo + off);
            }
            #pragma unroll
            for (int jh = 0; jh < 2; ++jh) {
                uint32_t off = sw64((uint32_t)((wn + jh*16 + lrow)*64 + (k0 + lkof)*2));
                uint32_t r[4];
                ldsm_x4(r, sb_hi + off);
                bh[2*jh][0]=r[0]; bh[2*jh][1]=r[2]; bh[2*jh+1][0]=r[1]; bh[2*jh+1][1]=r[3];
                ldsm_x4(r, sb_lo + off);
                bl[2*jh][0]=r[0]; bl[2*jh][1]=r[2]; bl[2*jh+1][0]=r[1]; bl[2*jh+1][1]=r[3];
            }
            #pragma unroll
            for (int i = 0; i < 2; ++i)
                #pragma unroll
                for (int j = 0; j < 4; ++j) {
                    mma16816(acc[i][j], ah[i], bh[j]);
                    mma16816(acc[i][j], ah[i], bl[j]);
                    mma16816(acc[i][j], al[i], bh[j]);
                }
        }
        __syncthreads();
    }

    // epilogue
    const int g = lane >> 2, tq = (lane & 3)*2;
    #pragma unroll
    for (int i = 0; i < 2; ++i) {
        #pragma unroll
        for (int half = 0; half < 2; ++half) {
            int m = m0 + wm + i*16 + g + half*8;
            if (m >= M) continue;
            #pragma unroll
            for (int j = 0; j < 4; ++j) {
                #pragma unroll
                for (int s = 0; s < 2; ++s) {
                    int n = n0 + wn + j*8 + tq + s;
                    if (n >= N) continue;
                    float x = acc[i][j][half*2 + s];
                    if (MODE == MODE_NONE) {
                        C[(size_t)m*ldc + n] = x;
                    } else if (MODE == MODE_ZRH) {
                        x += bias[n];
                        if (n < CD) {
                            p0[m*CD + n] = 1.f/(1.f + expf(-x));
                        } else if (n < 2*CD) {
                            int nn = n - CD;
                            float rn = (1.f/(1.f + expf(-x))) * p2[m*CD + nn];
                            split_bf(rn, &q0[m*CD + nn], &q1[m*CD + nn]);
                        } else {
                            p1[m*CD + (n - 2*CD)] = x;
                        }
                    } else if (MODE == MODE_GRU2) {
                        float hc = tanhf(x + p1[m*CD + n]);
                        float z  = p0[m*CD + n];
                        float nv = (1.f - z)*p2[m*CD + n] + z*hc;
                        p2[m*CD + n] = nv;
                        split_bf(nv, &q0[m*CD + n], &q1[m*CD + n]);
                    } else { // MODE_TANH
                        C[(size_t)m*ldc + n] = tanhf(x + bias[n]);
                    }
                }
            }
        }
    }
}

// ---------------- semantic-branch kernels ----------------
__global__ __launch_bounds__(256) void k_coeff() {
    __shared__ float fwh_s[CD];
    __shared__ float v_s[CD];
    int n = blockIdx.x;
    for (int i = threadIdx.x; i < CD; i += 256) {
        fwh_s[i] = d_fwh[n*CD + i];
        v_s[i]   = d_v[i];
    }
    __syncthreads();
    int warp = threadIdx.x >> 5, lane = threadIdx.x & 31;
    float c0 = d_c0s[0];
    for (int l = warp; l < LD; l += 8) {
        const float* fw = d_fwd + l*CD;
        float acc = 0.f;
        #pragma unroll 8
        for (int i = lane; i < CD; i += 32) {
            float p = fwh_s[i] * fw[i];
            float tv;
            asm("tanh.approx.f32 %0, %1;" : "=f"(tv) : "f"(p));
            acc += tv * v_s[i];
        }
        #pragma unroll
        for (int o = 16; o > 0; o >>= 1) acc += __shfl_xor_sync(0xffffffffu, acc, o);
        if (lane == 0) d_coeff[n*LD + l] = acc + c0;
    }
}

__global__ __launch_bounds__(256) void k_softmax() {
    int g = blockIdx.x*8 + (threadIdx.x >> 5);
    int lane = threadIdx.x & 31;
    if (g >= NP*LD/HW) return;
    float* p = d_coeff + g*HW;
    float vals[7];
    float mx = -1e30f;
    #pragma unroll
    for (int q = 0; q < 7; ++q) {
        int i = lane + q*32;
        vals[q] = (i < HW) ? p[i] : -1e30f;
        mx = fmaxf(mx, vals[q]);
    }
    #pragma unroll
    for (int o = 16; o > 0; o >>= 1) mx = fmaxf(mx, __shfl_xor_sync(0xffffffffu, mx, o));
    float s = 0.f;
    #pragma unroll
    for (int q = 0; q < 7; ++q) {
        int i = lane + q*32;
        if (i < HW) { vals[q] = expf(vals[q] - mx); s += vals[q]; }
    }
    #pragma unroll
    for (int o = 16; o > 0; o >>= 1) s += __shfl_xor_sync(0xffffffffu, s, o);
    float inv = 1.f / s;
    #pragma unroll
    for (int q = 0; q < 7; ++q) {
        int i = lane + q*32;
        if (i < HW) p[i] = vals[q]*inv;
    }
}

// g + nodes seed; writes fp32 nodes and bf16 splits of g and nodes
__global__ __launch_bounds__(256) void k_g(const float* __restrict__ img) {
    __shared__ float s[HW];
    int b = blockIdx.x / LD, l = blockIdx.x % LD;
    for (int tt = threadIdx.x; tt < HW; tt += 256)
        s[tt] = d_coeff[(b*HW + tt)*LD + l];
    __syncthreads();
    const float* xb = img + b*HW*CD;
    int c = threadIdx.x;
    float a0 = 0.f, a1 = 0.f, a2 = 0.f, a3 = 0.f;
    #pragma unroll 4
    for (int tt = 0; tt < HW; ++tt) {
        float w = s[tt];
        const float* xr = xb + tt*CD;
        a0 += w*xr[c]; a1 += w*xr[c+256]; a2 += w*xr[c+512]; a3 += w*xr[c+768];
    }
    int base = (b*LD + l)*CD + c;
    float vals[4] = {a0, a1, a2, a3};
    #pragma unroll
    for (int q = 0; q < 4; ++q) {
        int idx = base + q*256;
        d_nodes[idx] = vals[q];
        split_bf(vals[q], &c_g_h[idx], &c_g_l[idx]);
        c_nodes_h[idx] = c_g_h[idx];
        c_nodes_l[idx] = c_g_l[idx];
    }
}

// a = adj-combined nodes; writes bf16 split only
__global__ __launch_bounds__(256) void k_a(const float* __restrict__ adj) {
    __shared__ float ar[LD];
    int b = blockIdx.x / LD, nn = blockIdx.x % LD;
    if (threadIdx.x < LD) ar[threadIdx.x] = adj[nn*LD + threadIdx.x];
    __syncthreads();
    int c = threadIdx.x;
    const float* nb = d_nodes + b*LD*CD;
    float a0 = 0.f, a1 = 0.f, a2 = 0.f, a3 = 0.f;
    #pragma unroll 4
    for (int m = 0; m < LD; ++m) {
        float w = ar[m];
        const float* nr = nb + m*CD;
        a0 += w*nr[c]; a1 += w*nr[c+256]; a2 += w*nr[c+512]; a3 += w*nr[c+768];
    }
    int base = (b*LD + nn)*CD + c;
    float vals[4] = {a0, a1, a2, a3};
    #pragma unroll
    for (int q = 0; q < 4; ++q) {
        int idx = base + q*256;
        split_bf(vals[q], &c_a_h[idx], &c_a_l[idx]);
    }
}

// ---------------- host ----------------
struct Sym {
    float *fwd, *v, *c0s, *ball, *fwh, *coeff, *nodes, *zbuf, *hbuf;
    unsigned short *imgh, *imgl, *fc1h, *fc1l, *wembh, *wembl, *fc2h, *fc2l;
    unsigned short *wallh, *walll, *u3h, *u3l, *u5h, *u5l, *fcoh, *fcol;
    unsigned short *ndh, *ndl, *ah, *al, *rnh, *rnl, *gh, *gl;
};
static void get_syms(Sym& S) {
    cudaGetSymbolAddress((void**)&S.fwd, d_fwd);
    cudaGetSymbolAddress((void**)&S.v, d_v);
    cudaGetSymbolAddress((void**)&S.c0s, d_c0s);
    cudaGetSymbolAddress((void**)&S.ball, d_ball);
    cudaGetSymbolAddress((void**)&S.fwh, d_fwh);
    cudaGetSymbolAddress((void**)&S.coeff, d_coeff);
    cudaGetSymbolAddress((void**)&S.nodes, d_nodes);
    cudaGetSymbolAddress((void**)&S.zbuf, d_zbuf);
    cudaGetSymbolAddress((void**)&S.hbuf, d_hbuf);
    cudaGetSymbolAddress((void**)&S.imgh, c_img_h);   cudaGetSymbolAddress((void**)&S.imgl, c_img_l);
    cudaGetSymbolAddress((void**)&S.fc1h, c_fc1_h);   cudaGetSymbolAddress((void**)&S.fc1l, c_fc1_l);
    cudaGetSymbolAddress((void**)&S.wembh, c_wemb_h); cudaGetSymbolAddress((void**)&S.wembl, c_wemb_l);
    cudaGetSymbolAddress((void**)&S.fc2h, c_fc2_h);   cudaGetSymbolAddress((void**)&S.fc2l, c_fc2_l);
    cudaGetSymbolAddress((void**)&S.wallh, c_wall_h); cudaGetSymbolAddress((void**)&S.walll, c_wall_l);
    cudaGetSymbolAddress((void**)&S.u3h, c_u3_h);     cudaGetSymbolAddress((void**)&S.u3l, c_u3_l);
    cudaGetSymbolAddress((void**)&S.u5h, c_u5_h);     cudaGetSymbolAddress((void**)&S.u5l, c_u5_l);
    cudaGetSymbolAddress((void**)&S.fcoh, c_fco_h);   cudaGetSymbolAddress((void**)&S.fcol, c_fco_l);
    cudaGetSymbolAddress((void**)&S.ndh, c_nodes_h);  cudaGetSymbolAddress((void**)&S.ndl, c_nodes_l);
    cudaGetSymbolAddress((void**)&S.ah, c_a_h);       cudaGetSymbolAddress((void**)&S.al, c_a_l);
    cudaGetSymbolAddress((void**)&S.rnh, c_rn_h);     cudaGetSymbolAddress((void**)&S.rnl, c_rn_l);
    cudaGetSymbolAddress((void**)&S.gh, c_g_h);       cudaGetSymbolAddress((void**)&S.gl, c_g_l);
}

template<int MODE>
static void tg(const unsigned short* Ah, const unsigned short* Al, int lda,
               const unsigned short* Bh, const unsigned short* Bl, int ldb,
               const unsigned short* A2h, const unsigned short* A2l, int lda2,
               const unsigned short* B2h, const unsigned short* B2l, int ldb2,
               int b2mask, int n2lim, int M, int N, int Kpad,
               const float* bias, float* p0, float* p1, float* p2,
               unsigned short* q0, unsigned short* q1, float* C, int ldc) {
    dim3 grid((N + TN - 1)/TN, (M + TM - 1)/TM);
    t_gemm<MODE><<<grid, 256>>>(Ah, Al, lda, Bh, Bl, ldb, A2h, A2l, lda2,
                                B2h, B2l, ldb2, b2mask, n2lim, M, N, Kpad,
                                bias, p0, p1, p2, q0, q1, C, ldc);
}

extern "C" void kernel_launch(void* const* d_in, const int* in_sizes, int n_in,
                              void* d_out, int out_size) {
    const float* img  = (const float*)d_in[0];
    const float* wemb = (const float*)d_in[1];
    const float* adj  = (const float*)d_in[2];
    const float* fc1  = (const float*)d_in[3];
    const float* fc2  = (const float*)d_in[4];
    const float* fc3  = (const float*)d_in[5];
    const float* fc3b = (const float*)d_in[6];
    const float* fca  = (const float*)d_in[7];
    const float* fcab = (const float*)d_in[8];
    const float* w3   = (const float*)d_in[9];
    const float* b3   = (const float*)d_in[10];
    const float* u3   = (const float*)d_in[11];
    const float* u3b  = (const float*)d_in[12];
    const float* w4   = (const float*)d_in[13];
    const float* b4   = (const float*)d_in[14];
    const float* w5   = (const float*)d_in[15];
    const float* b5   = (const float*)d_in[16];
    const float* u5   = (const float*)d_in[17];
    const float* u5b  = (const float*)d_in[18];
    const float* fco  = (const float*)d_in[19];
    const float* fcob = (const float*)d_in[20];
    float* out = (float*)d_out;

    Sym S; get_syms(S);

    // 1-3: convert fwh operands (launch #4 = fwh GEMM for ncu capture)
    k_conv<<<1184, 256>>>(fc1,  S.fc1h,  S.fc1l,  CD, CD, CD);
    k_conv<<<1184, 256>>>(img,  S.imgh,  S.imgl,  NP, CD, CD);
    k_conv<<<160, 256>>>(wemb, S.wembh, S.wembl, LD, WDIM, WPAD);
    // 4: f_wh = x @ fc1^T
    tg<MODE_NONE>(S.imgh, S.imgl, CD, S.fc1h, S.fc1l, CD,
                  nullptr, nullptr, 0, nullptr, nullptr, 0, NOMASK, 0,
                  NP, CD, CD, nullptr, nullptr, nullptr, nullptr, nullptr, nullptr,
                  S.fwh, CD);
    // 5-6: f_wd = wemb @ fc2^T
    k_conv<<<640, 256>>>(fc2, S.fc2h, S.fc2l, CD, WDIM, WPAD);
    tg<MODE_NONE>(S.wembh, S.wembl, WPAD, S.fc2h, S.fc2l, WPAD,
                  nullptr, nullptr, 0, nullptr, nullptr, 0, NOMASK, 0,
                  LD, CD, WPAD, nullptr, nullptr, nullptr, nullptr, nullptr, nullptr,
                  S.fwd, CD);
    // 7-11: semantic chain
    k_v<<<4, 256>>>(fc3, fca);
    k_c0<<<1, 256>>>(fc3b, fca, fcab);
    k_coeff<<<NP, 256>>>();
    k_softmax<<<40, 256>>>();
    k_g<<<BT*LD, 256>>>(img);
    // 12-16: GGNN weight prep
    k_wsum<<<3072, 256>>>(w3, w4, w5);
    k_bias<<<4, 256>>>(b3, u3b, b4, b5, u5b);
    k_conv<<<1184, 256>>>(u3,  S.u3h,  S.u3l,  CD, CD, CD);
    k_conv<<<1184, 256>>>(u5,  S.u5h,  S.u5l,  CD, CD, CD);
    k_conv<<<1184, 256>>>(fco, S.fcoh, S.fcol, OD, 2*CD, 2*CD);

    for (int step = 0; step < 3; ++step) {
        k_a<<<BT*LD, 256>>>(adj);
        // z | rn | h-preact  (pass2: nodes @ u3^T replayed over z,r col-blocks)
        tg<MODE_ZRH>(S.ah, S.al, CD, S.wallh, S.walll, CD,
                     S.ndh, S.ndl, CD, S.u3h, S.u3l, CD, CD-1, 2*CD,
                     NR, 3*CD, CD, S.ball, S.zbuf, S.hbuf, S.nodes,
                     S.rnh, S.rnl, nullptr, 0);
        // nodes = (1-z)*nodes + z*tanh(rn@u5^T + h)
        tg<MODE_GRU2>(S.rnh, S.rnl, CD, S.u5h, S.u5l, CD,
                      nullptr, nullptr, 0, nullptr, nullptr, 0, NOMASK, 0,
                      NR, CD, CD, nullptr, S.zbuf, S.hbuf, S.nodes,
                      S.ndh, S.ndl, nullptr, 0);
    }

    // out = tanh([nodes, g] @ fco^T + fco_b): dual-K over fco column halves
    tg<MODE_TANH>(S.ndh, S.ndl, CD, S.fcoh, S.fcol, 2*CD,
                  S.gh, S.gl, CD, S.fcoh + CD, S.fcol + CD, 2*CD, NOMASK, NOMASK,
                  NR, OD, CD, fcob, nullptr, nullptr, nullptr, nullptr, nullptr,
                  out, OD);
}

// round 10
// speedup vs baseline: 2.4978x; 1.1210x over previous
#include <cuda_runtime.h>
#include <cuda_bf16.h>
#include <math.h>
#include <stdint.h>

#define CD 1024
#define LD 80
#define WDIM 300
#define WPAD 320
#define HW 196
#define BT 4
#define NP 784
#define OD 2048
#define NR (BT*LD)
#define NE (NR*CD)

#define MODE_NONE 0
#define MODE_ZRH  1
#define MODE_GRU2 2
#define MODE_TANH 3

#define TM 64
#define TN 64
#define NOMASK 0x7FFFFFFF

// ---------------- fp32 scratch ----------------
__device__ float d_fwd[LD*CD];
__device__ float d_v[CD];
__device__ float d_c0s[1];
__device__ float d_ball[3*CD];
__device__ float d_fwh[NP*CD];
__device__ float d_coeff[NP*LD];
__device__ float d_nodes[NE];
__device__ float d_zbuf[NE];
__device__ float d_hbuf[NE];

// ---------------- bf16 hi/lo operand buffers ----------------
__device__ unsigned short c_img_h[NP*CD],    c_img_l[NP*CD];
__device__ unsigned short c_fc1_h[CD*CD],    c_fc1_l[CD*CD];
__device__ unsigned short c_wemb_h[LD*WPAD], c_wemb_l[LD*WPAD];
__device__ unsigned short c_fc2_h[CD*WPAD],  c_fc2_l[CD*WPAD];
__device__ unsigned short c_wall_h[3*CD*CD], c_wall_l[3*CD*CD];
__device__ unsigned short c_u3_h[CD*CD],     c_u3_l[CD*CD];
__device__ unsigned short c_u5_h[CD*CD],     c_u5_l[CD*CD];
__device__ unsigned short c_fco_h[OD*2*CD],  c_fco_l[OD*2*CD];
__device__ unsigned short c_nodes_h[NE],     c_nodes_l[NE];
__device__ unsigned short c_a_h[NE],         c_a_l[NE];
__device__ unsigned short c_rn_h[NE],        c_rn_l[NE];
__device__ unsigned short c_g_h[NE],         c_g_l[NE];

// ---------------- helpers ----------------
__device__ __forceinline__ uint32_t smem_to_u32(const void* p) {
    uint32_t a;
    asm("{ .reg .u64 t; cvta.to.shared.u64 t, %1; cvt.u32.u64 %0, t; }" : "=r"(a) : "l"(p));
    return a;
}
__device__ __forceinline__ void split_bf(float v, unsigned short* h, unsigned short* l) {
    __nv_bfloat16 hb = __float2bfloat16(v);
    *h = __bfloat16_as_ushort(hb);
    *l = __bfloat16_as_ushort(__float2bfloat16(v - __bfloat162float(hb)));
}
__device__ __forceinline__ void ldsm_x4(uint32_t* r, uint32_t addr) {
    asm volatile("ldmatrix.sync.aligned.m8n8.x4.shared.b16 {%0,%1,%2,%3}, [%4];"
        : "=r"(r[0]), "=r"(r[1]), "=r"(r[2]), "=r"(r[3]) : "r"(addr));
}
__device__ __forceinline__ void mma16816(float* c, const uint32_t* a, const uint32_t* b) {
    asm volatile("mma.sync.aligned.m16n8k16.row.col.f32.bf16.bf16.f32 "
        "{%0,%1,%2,%3}, {%4,%5,%6,%7}, {%8,%9}, {%0,%1,%2,%3};"
        : "+f"(c[0]), "+f"(c[1]), "+f"(c[2]), "+f"(c[3])
        : "r"(a[0]), "r"(a[1]), "r"(a[2]), "r"(a[3]), "r"(b[0]), "r"(b[1]));
}
__device__ __forceinline__ void cpasync16(uint32_t dst, const void* src, bool ok) {
    asm volatile("cp.async.cg.shared.global [%0], [%1], 16, %2;"
        :: "r"(dst), "l"(src), "r"(ok ? 16 : 0) : "memory");
}
__device__ __forceinline__ void cp_commit() {
    asm volatile("cp.async.commit_group;" ::: "memory");
}
template<int N> __device__ __forceinline__ void cp_waitN() {
    asm volatile("cp.async.wait_group %0;" :: "n"(N) : "memory");
}
__device__ __forceinline__ uint32_t sw64(uint32_t off) {
    return off ^ ((off >> 3) & 0x30);
}

// ---------------- merged prep: all operand converts + wsum + bias (one launch) -------
__global__ void k_prep(const float* __restrict__ fc1, const float* __restrict__ img,
                       const float* __restrict__ wemb, const float* __restrict__ fc2,
                       const float* __restrict__ u3, const float* __restrict__ u5,
                       const float* __restrict__ fco,
                       const float* __restrict__ w3, const float* __restrict__ w4,
                       const float* __restrict__ w5,
                       const float* __restrict__ b3, const float* __restrict__ u3b,
                       const float* __restrict__ b4, const float* __restrict__ b5,
                       const float* __restrict__ u5b) {
    const int o1 = CD*CD;                 // fc1
    const int o2 = o1 + NP*CD;            // img
    const int o3 = o2 + LD*WPAD;          // wemb (padded)
    const int o4 = o3 + CD*WPAD;          // fc2  (padded)
    const int o5 = o4 + CD*CD;            // u3
    const int o6 = o5 + CD*CD;            // u5
    const int o7 = o6 + OD*2*CD;          // fco
    const int o8 = o7 + 3*CD*CD;          // wsum
    const int o9 = o8 + 3*CD;             // bias
    int stride = gridDim.x * blockDim.x;
    for (int i = blockIdx.x*blockDim.x + threadIdx.x; i < o9; i += stride) {
        if (i < o1) {
            split_bf(fc1[i], &c_fc1_h[i], &c_fc1_l[i]);
        } else if (i < o2) {
            int j = i - o1;
            split_bf(img[j], &c_img_h[j], &c_img_l[j]);
        } else if (i < o3) {
            int j = i - o2, r = j / WPAD, c = j - r*WPAD;
            float v = (c < WDIM) ? wemb[r*WDIM + c] : 0.f;
            split_bf(v, &c_wemb_h[j], &c_wemb_l[j]);
        } else if (i < o4) {
            int j = i - o3, r = j / WPAD, c = j - r*WPAD;
            float v = (c < WDIM) ? fc2[r*WDIM + c] : 0.f;
            split_bf(v, &c_fc2_h[j], &c_fc2_l[j]);
        } else if (i < o5) {
            int j = i - o4;
            split_bf(u3[j], &c_u3_h[j], &c_u3_l[j]);
        } else if (i < o6) {
            int j = i - o5;
            split_bf(u5[j], &c_u5_h[j], &c_u5_l[j]);
        } else if (i < o7) {
            int j = i - o6;
            split_bf(fco[j], &c_fco_h[j], &c_fco_l[j]);
        } else if (i < o8) {
            int j = i - o7;
            int which = j / (CD*CD);
            int rem = j - which*(CD*CD);
            int r = rem >> 10, c = rem & (CD-1);
            const float* w = (which==0) ? w3 : (which==1) ? w4 : w5;
            float val = w[r*2*CD + c] + w[r*2*CD + CD + c];
            split_bf(val, &c_wall_h[j], &c_wall_l[j]);
        } else {
            int j = i - o8;
            int which = j >> 10, c = j & (CD-1);
            if (which == 0)      d_ball[c]        = b3[c] + u3b[c];
            else if (which == 1) d_ball[CD + c]   = b4[c] + u3b[c]; // torch bug kept
            else                 d_ball[2*CD + c] = b5[c] + u5b[c];
        }
    }
}

// v[i] = fca @ fc3 (blocks 0-3); c0 = fca·fc3_b + fca_b (block 4)
__global__ void k_vc(const float* __restrict__ fc3_w, const float* __restrict__ fca_w,
                     const float* __restrict__ fc3_b, const float* __restrict__ fca_b) {
    if (blockIdx.x < 4) {
        __shared__ float fs[CD];
        for (int j = threadIdx.x; j < CD; j += 256) fs[j] = fca_w[j];
        __syncthreads();
        int i = blockIdx.x*256 + threadIdx.x;
        float acc = 0.f;
        #pragma unroll 8
        for (int j = 0; j < CD; ++j) acc += fs[j] * fc3_w[j*CD + i];
        d_v[i] = acc;
    } else {
        __shared__ float red[8];
        float acc = 0.f;
        for (int j = threadIdx.x; j < CD; j += 256) acc += fc3_b[j] * fca_w[j];
        #pragma unroll
        for (int o = 16; o > 0; o >>= 1) acc += __shfl_xor_sync(0xffffffffu, acc, o);
        if ((threadIdx.x & 31) == 0) red[threadIdx.x >> 5] = acc;
        __syncthreads();
        if (threadIdx.x == 0) {
            float s = 0.f;
            #pragma unroll
            for (int q = 0; q < 8; ++q) s += red[q];
            d_c0s[0] = s + fca_b[0];
        }
    }
}

// ---------------- tensor GEMM: 64x64 tile, 4 warps, 3-stage cp.async ring ------------
// C = epi( A@B^T [+ A2@B2^T] + bias ); fp32 via bf16 split (hh + hl + lh).
// smem: 3 stages x (A hi 4K | A lo 4K | B hi 4K | B lo 4K) = 49152 B static.
template<int MODE>
__global__ __launch_bounds__(128) void t_gemm(
    const unsigned short* __restrict__ Ah, const unsigned short* __restrict__ Al, int lda,
    const unsigned short* __restrict__ Bh, const unsigned short* __restrict__ Bl, int ldb,
    const unsigned short* __restrict__ A2h, const unsigned short* __restrict__ A2l, int lda2,
    const unsigned short* __restrict__ B2h, const unsigned short* __restrict__ B2l, int ldb2,
    int b2mask, int n2_limit,
    int M, int N, int Kpad,
    const float* __restrict__ bias,
    float* __restrict__ p0, float* __restrict__ p1, float* __restrict__ p2,
    unsigned short* __restrict__ q0, unsigned short* __restrict__ q1,
    float* __restrict__ C, int ldc)
{
    __shared__ __align__(128) char dsm[49152];
    uint32_t sbase = smem_to_u32(dsm);

    const int tid = threadIdx.x;
    const int wid = tid >> 5;
    const int lane = tid & 31;
    const int m0 = blockIdx.y * TM;
    const int n0 = blockIdx.x * TN;
    const int wm = (wid >> 1) * 32;
    const int wn = (wid & 1) * 32;

    const int qm = lane >> 3, rr = lane & 7;
    const int lrow = (qm & 1)*8 + rr;
    const int lkof = (qm >> 1)*8;

    float acc[2][4][4];
    #pragma unroll
    for (int i = 0; i < 2; ++i)
        #pragma unroll
        for (int j = 0; j < 4; ++j)
            #pragma unroll
            for (int s = 0; s < 4; ++s) acc[i][j][s] = 0.f;

    const int nst1 = Kpad >> 5;
    const bool do2 = (A2h != nullptr) && (n0 < n2_limit);
    const int nst = do2 ? 2*nst1 : nst1;

    // stage: 8 cp.async per thread into ring buffer (t % 3)
    auto stage = [&](int t) {
        int pass = (t >= nst1) ? 1 : 0;
        int k0 = (t - pass*nst1) << 5;
        const unsigned short* pAh = pass ? A2h : Ah;
        const unsigned short* pAl = pass ? A2l : Al;
        const unsigned short* pBh = pass ? B2h : Bh;
        const unsigned short* pBl = pass ? B2l : Bl;
        int la = pass ? lda2 : lda;
        int lb = pass ? ldb2 : ldb;
        int bm = pass ? b2mask : NOMASK;
        uint32_t sb = sbase + (t % 3) * 16384;
        #pragma unroll
        for (int qq = 0; qq < 8; ++qq) {
            int c = tid + (qq << 7);
            if (c < 512) {             // A: hi [0,256) lo [256,512)
                int part = c >> 8;
                int sub = c & 255;
                int row = sub >> 2, quad = sub & 3;
                int gr = m0 + row;
                bool ok = gr < M;
                const unsigned short* s = (part ? pAl : pAh)
                                          + (size_t)(ok ? gr : 0)*la + k0 + quad*8;
                uint32_t off = sw64((uint32_t)(row*64 + quad*16));
                cpasync16(sb + part*4096 + off, s, ok);
            } else {                   // B: hi [512,768) lo [768,1024)
                int cb = c - 512;
                int part = cb >> 8;
                int sub = cb & 255;
                int row = sub >> 2, quad = sub & 3;
                int gn = n0 + row;
                bool ok = gn < N;
                int er = (ok ? gn : 0) & bm;
                const unsigned short* s = (part ? pBl : pBh)
                                          + (size_t)er*lb + k0 + quad*8;
                uint32_t off = sw64((uint32_t)(row*64 + quad*16));
                cpasync16(sb + 8192 + part*4096 + off, s, ok);
            }
        }
        cp_commit();
    };

    stage(0);
    if (nst > 1) stage(1);
    for (int t = 0; t < nst; ++t) {
        if (t + 2 < nst) { stage(t + 2); cp_waitN<2>(); }
        else if (t + 1 < nst) cp_waitN<1>();
        else cp_waitN<0>();
        __syncthreads();
        uint32_t sb = sbase + (t % 3) * 16384;
        uint32_t sa_hi = sb, sa_lo = sb + 4096, sb_hi = sb + 8192, sb_lo = sb + 12288;
        #pragma unroll
        for (int k0 = 0; k0 < 32; k0 += 16) {
            uint32_t ah[2][4], al[2][4], bh[4][2], bl[4][2];
            #pragma unroll
            for (int i = 0; i < 2; ++i) {
                uint32_t off = sw64((uint32_t)((wm + i*16 + lrow)*64 + (k0 + lkof)*2));
                ldsm_x4(ah[i], sa_hi + off);
                ldsm_x4(al[i], sa_lo + off);
            }
            #pragma unroll
            for (int jh = 0; jh < 2; ++jh) {
                uint32_t off = sw64((uint32_t)((wn + jh*16 + lrow)*64 + (k0 + lkof)*2));
                uint32_t r[4];
                ldsm_x4(r, sb_hi + off);
                bh[2*jh][0]=r[0]; bh[2*jh][1]=r[2]; bh[2*jh+1][0]=r[1]; bh[2*jh+1][1]=r[3];
                ldsm_x4(r, sb_lo + off);
                bl[2*jh][0]=r[0]; bl[2*jh][1]=r[2]; bl[2*jh+1][0]=r[1]; bl[2*jh+1][1]=r[3];
            }
            #pragma unroll
            for (int i = 0; i < 2; ++i)
                #pragma unroll
                for (int j = 0; j < 4; ++j) {
                    mma16816(acc[i][j], ah[i], bh[j]);
                    mma16816(acc[i][j], ah[i], bl[j]);
                    mma16816(acc[i][j], al[i], bh[j]);
                }
        }
        __syncthreads();
    }

    // epilogue
    const int g = lane >> 2, tq = (lane & 3)*2;
    #pragma unroll
    for (int i = 0; i < 2; ++i) {
        #pragma unroll
        for (int half = 0; half < 2; ++half) {
            int m = m0 + wm + i*16 + g + half*8;
            if (m >= M) continue;
            #pragma unroll
            for (int j = 0; j < 4; ++j) {
                #pragma unroll
                for (int s = 0; s < 2; ++s) {
                    int n = n0 + wn + j*8 + tq + s;
                    if (n >= N) continue;
                    float x = acc[i][j][half*2 + s];
                    if (MODE == MODE_NONE) {
                        C[(size_t)m*ldc + n] = x;
                    } else if (MODE == MODE_ZRH) {
                        x += bias[n];
                        if (n < CD) {
                            p0[m*CD + n] = 1.f/(1.f + expf(-x));
                        } else if (n < 2*CD) {
                            int nn = n - CD;
                            float rn = (1.f/(1.f + expf(-x))) * p2[m*CD + nn];
                            split_bf(rn, &q0[m*CD + nn], &q1[m*CD + nn]);
                        } else {
                            p1[m*CD + (n - 2*CD)] = x;
                        }
                    } else if (MODE == MODE_GRU2) {
                        float hc = tanhf(x + p1[m*CD + n]);
                        float z  = p0[m*CD + n];
                        float nv = (1.f - z)*p2[m*CD + n] + z*hc;
                        p2[m*CD + n] = nv;
                        split_bf(nv, &q0[m*CD + n], &q1[m*CD + n]);
                    } else { // MODE_TANH
                        C[(size_t)m*ldc + n] = tanhf(x + bias[n]);
                    }
                }
            }
        }
    }
}

// ---------------- semantic-branch kernels ----------------
__global__ __launch_bounds__(256) void k_coeff() {
    __shared__ float fwh_s[CD];
    __shared__ float v_s[CD];
    int n = blockIdx.x;
    for (int i = threadIdx.x; i < CD; i += 256) {
        fwh_s[i] = d_fwh[n*CD + i];
        v_s[i]   = d_v[i];
    }
    __syncthreads();
    int warp = threadIdx.x >> 5, lane = threadIdx.x & 31;
    float c0 = d_c0s[0];
    for (int l = warp; l < LD; l += 8) {
        const float* fw = d_fwd + l*CD;
        float acc = 0.f;
        #pragma unroll 8
        for (int i = lane; i < CD; i += 32) {
            float p = fwh_s[i] * fw[i];
            float tv;
            asm("tanh.approx.f32 %0, %1;" : "=f"(tv) : "f"(p));
            acc += tv * v_s[i];
        }
        #pragma unroll
        for (int o = 16; o > 0; o >>= 1) acc += __shfl_xor_sync(0xffffffffu, acc, o);
        if (lane == 0) d_coeff[n*LD + l] = acc + c0;
    }
}

__global__ __launch_bounds__(256) void k_softmax() {
    int g = blockIdx.x*8 + (threadIdx.x >> 5);
    int lane = threadIdx.x & 31;
    if (g >= NP*LD/HW) return;
    float* p = d_coeff + g*HW;
    float vals[7];
    float mx = -1e30f;
    #pragma unroll
    for (int q = 0; q < 7; ++q) {
        int i = lane + q*32;
        vals[q] = (i < HW) ? p[i] : -1e30f;
        mx = fmaxf(mx, vals[q]);
    }
    #pragma unroll
    for (int o = 16; o > 0; o >>= 1) mx = fmaxf(mx, __shfl_xor_sync(0xffffffffu, mx, o));
    float s = 0.f;
    #pragma unroll
    for (int q = 0; q < 7; ++q) {
        int i = lane + q*32;
        if (i < HW) { vals[q] = expf(vals[q] - mx); s += vals[q]; }
    }
    #pragma unroll
    for (int o = 16; o > 0; o >>= 1) s += __shfl_xor_sync(0xffffffffu, s, o);
    float inv = 1.f / s;
    #pragma unroll
    for (int q = 0; q < 7; ++q) {
        int i = lane + q*32;
        if (i < HW) p[i] = vals[q]*inv;
    }
}

__global__ __launch_bounds__(256) void k_g(const float* __restrict__ img) {
    __shared__ float s[HW];
    int b = blockIdx.x / LD, l = blockIdx.x % LD;
    for (int tt = threadIdx.x; tt < HW; tt += 256)
        s[tt] = d_coeff[(b*HW + tt)*LD + l];
    __syncthreads();
    const float* xb = img + b*HW*CD;
    int c = threadIdx.x;
    float a0 = 0.f, a1 = 0.f, a2 = 0.f, a3 = 0.f;
    #pragma unroll 4
    for (int tt = 0; tt < HW; ++tt) {
        float w = s[tt];
        const float* xr = xb + tt*CD;
        a0 += w*xr[c]; a1 += w*xr[c+256]; a2 += w*xr[c+512]; a3 += w*xr[c+768];
    }
    int base = (b*LD + l)*CD + c;
    float vals[4] = {a0, a1, a2, a3};
    #pragma unroll
    for (int q = 0; q < 4; ++q) {
        int idx = base + q*256;
        d_nodes[idx] = vals[q];
        split_bf(vals[q], &c_g_h[idx], &c_g_l[idx]);
        c_nodes_h[idx] = c_g_h[idx];
        c_nodes_l[idx] = c_g_l[idx];
    }
}

__global__ __launch_bounds__(256) void k_a(const float* __restrict__ adj) {
    __shared__ float ar[LD];
    int b = blockIdx.x / LD, nn = blockIdx.x % LD;
    if (threadIdx.x < LD) ar[threadIdx.x] = adj[nn*LD + threadIdx.x];
    __syncthreads();
    int c = threadIdx.x;
    const float* nb = d_nodes + b*LD*CD;
    float a0 = 0.f, a1 = 0.f, a2 = 0.f, a3 = 0.f;
    #pragma unroll 4
    for (int m = 0; m < LD; ++m) {
        float w = ar[m];
        const float* nr = nb + m*CD;
        a0 += w*nr[c]; a1 += w*nr[c+256]; a2 += w*nr[c+512]; a3 += w*nr[c+768];
    }
    int base = (b*LD + nn)*CD + c;
    float vals[4] = {a0, a1, a2, a3};
    #pragma unroll
    for (int q = 0; q < 4; ++q) {
        int idx = base + q*256;
        split_bf(vals[q], &c_a_h[idx], &c_a_l[idx]);
    }
}

// ---------------- host ----------------
struct Sym {
    float *fwd, *v, *c0s, *ball, *fwh, *coeff, *nodes, *zbuf, *hbuf;
    unsigned short *imgh, *imgl, *fc1h, *fc1l, *wembh, *wembl, *fc2h, *fc2l;
    unsigned short *wallh, *walll, *u3h, *u3l, *u5h, *u5l, *fcoh, *fcol;
    unsigned short *ndh, *ndl, *ah, *al, *rnh, *rnl, *gh, *gl;
};
static void get_syms(Sym& S) {
    cudaGetSymbolAddress((void**)&S.fwd, d_fwd);
    cudaGetSymbolAddress((void**)&S.v, d_v);
    cudaGetSymbolAddress((void**)&S.c0s, d_c0s);
    cudaGetSymbolAddress((void**)&S.ball, d_ball);
    cudaGetSymbolAddress((void**)&S.fwh, d_fwh);
    cudaGetSymbolAddress((void**)&S.coeff, d_coeff);
    cudaGetSymbolAddress((void**)&S.nodes, d_nodes);
    cudaGetSymbolAddress((void**)&S.zbuf, d_zbuf);
    cudaGetSymbolAddress((void**)&S.hbuf, d_hbuf);
    cudaGetSymbolAddress((void**)&S.imgh, c_img_h);   cudaGetSymbolAddress((void**)&S.imgl, c_img_l);
    cudaGetSymbolAddress((void**)&S.fc1h, c_fc1_h);   cudaGetSymbolAddress((void**)&S.fc1l, c_fc1_l);
    cudaGetSymbolAddress((void**)&S.wembh, c_wemb_h); cudaGetSymbolAddress((void**)&S.wembl, c_wemb_l);
    cudaGetSymbolAddress((void**)&S.fc2h, c_fc2_h);   cudaGetSymbolAddress((void**)&S.fc2l, c_fc2_l);
    cudaGetSymbolAddress((void**)&S.wallh, c_wall_h); cudaGetSymbolAddress((void**)&S.walll, c_wall_l);
    cudaGetSymbolAddress((void**)&S.u3h, c_u3_h);     cudaGetSymbolAddress((void**)&S.u3l, c_u3_l);
    cudaGetSymbolAddress((void**)&S.u5h, c_u5_h);     cudaGetSymbolAddress((void**)&S.u5l, c_u5_l);
    cudaGetSymbolAddress((void**)&S.fcoh, c_fco_h);   cudaGetSymbolAddress((void**)&S.fcol, c_fco_l);
    cudaGetSymbolAddress((void**)&S.ndh, c_nodes_h);  cudaGetSymbolAddress((void**)&S.ndl, c_nodes_l);
    cudaGetSymbolAddress((void**)&S.ah, c_a_h);       cudaGetSymbolAddress((void**)&S.al, c_a_l);
    cudaGetSymbolAddress((void**)&S.rnh, c_rn_h);     cudaGetSymbolAddress((void**)&S.rnl, c_rn_l);
    cudaGetSymbolAddress((void**)&S.gh, c_g_h);       cudaGetSymbolAddress((void**)&S.gl, c_g_l);
}

template<int MODE>
static void tg(const unsigned short* Ah, const unsigned short* Al, int lda,
               const unsigned short* Bh, const unsigned short* Bl, int ldb,
               const unsigned short* A2h, const unsigned short* A2l, int lda2,
               const unsigned short* B2h, const unsigned short* B2l, int ldb2,
               int b2mask, int n2lim, int M, int N, int Kpad,
               const float* bias, float* p0, float* p1, float* p2,
               unsigned short* q0, unsigned short* q1, float* C, int ldc) {
    dim3 grid((N + TN - 1)/TN, (M + TM - 1)/TM);
    t_gemm<MODE><<<grid, 128>>>(Ah, Al, lda, Bh, Bl, ldb, A2h, A2l, lda2,
                                B2h, B2l, ldb2, b2mask, n2lim, M, N, Kpad,
                                bias, p0, p1, p2, q0, q1, C, ldc);
}

extern "C" void kernel_launch(void* const* d_in, const int* in_sizes, int n_in,
                              void* d_out, int out_size) {
    const float* img  = (const float*)d_in[0];
    const float* wemb = (const float*)d_in[1];
    const float* adj  = (const float*)d_in[2];
    const float* fc1  = (const float*)d_in[3];
    const float* fc2  = (const float*)d_in[4];
    const float* fc3  = (const float*)d_in[5];
    const float* fc3b = (const float*)d_in[6];
    const float* fca  = (const float*)d_in[7];
    const float* fcab = (const float*)d_in[8];
    const float* w3   = (const float*)d_in[9];
    const float* b3   = (const float*)d_in[10];
    const float* u3   = (const float*)d_in[11];
    const float* u3b  = (const float*)d_in[12];
    const float* w4   = (const float*)d_in[13];
    const float* b4   = (const float*)d_in[14];
    const float* w5   = (const float*)d_in[15];
    const float* b5   = (const float*)d_in[16];
    const float* u5   = (const float*)d_in[17];
    const float* u5b  = (const float*)d_in[18];
    const float* fco  = (const float*)d_in[19];
    const float* fcob = (const float*)d_in[20];
    float* out = (float*)d_out;

    Sym S; get_syms(S);

    // 1: all converts + wsum + bias
    k_prep<<<2048, 256>>>(fc1, img, wemb, fc2, u3, u5, fco,
                          w3, w4, w5, b3, u3b, b4, b5, u5b);
    // 2: v + c0
    k_vc<<<5, 256>>>(fc3, fca, fc3b, fcab);
    // 3: f_wd = wemb @ fc2^T
    tg<MODE_NONE>(S.wembh, S.wembl, WPAD, S.fc2h, S.fc2l, WPAD,
                  nullptr, nullptr, 0, nullptr, nullptr, 0, NOMASK, 0,
                  LD, CD, WPAD, nullptr, nullptr, nullptr, nullptr, nullptr, nullptr,
                  S.fwd, CD);
    // 4: f_wh = x @ fc1^T   (ncu capture slot)
    tg<MODE_NONE>(S.imgh, S.imgl, CD, S.fc1h, S.fc1l, CD,
                  nullptr, nullptr, 0, nullptr, nullptr, 0, NOMASK, 0,
                  NP, CD, CD, nullptr, nullptr, nullptr, nullptr, nullptr, nullptr,
                  S.fwh, CD);
    // 5-7: semantic chain
    k_coeff<<<NP, 256>>>();
    k_softmax<<<40, 256>>>();
    k_g<<<BT*LD, 256>>>(img);

    // GGNN
    for (int step = 0; step < 3; ++step) {
        k_a<<<BT*LD, 256>>>(adj);
        tg<MODE_ZRH>(S.ah, S.al, CD, S.wallh, S.walll, CD,
                     S.ndh, S.ndl, CD, S.u3h, S.u3l, CD, CD-1, 2*CD,
                     NR, 3*CD, CD, S.ball, S.zbuf, S.hbuf, S.nodes,
                     S.rnh, S.rnl, nullptr, 0);
        tg<MODE_GRU2>(S.rnh, S.rnl, CD, S.u5h, S.u5l, CD,
                      nullptr, nullptr, 0, nullptr, nullptr, 0, NOMASK, 0,
                      NR, CD, CD, nullptr, S.zbuf, S.hbuf, S.nodes,
                      S.ndh, S.ndl, nullptr, 0);
    }

    // out = tanh([nodes, g] @ fco^T + fco_b): dual-K over fco column halves
    tg<MODE_TANH>(S.ndh, S.ndl, CD, S.fcoh, S.fcol, 2*CD,
                  S.gh, S.gl, CD, S.fcoh + CD, S.fcol + CD, 2*CD, NOMASK, NOMASK,
                  NR, OD, CD, fcob, nullptr, nullptr, nullptr, nullptr, nullptr,
                  out, OD);
}

// round 11
// speedup vs baseline: 2.6388x; 1.0564x over previous
#include <cuda_runtime.h>
#include <cuda_bf16.h>
#include <math.h>
#include <stdint.h>

#define CD 1024
#define LD 80
#define WDIM 300
#define WPAD 320
#define HW 196
#define BT 4
#define NP 784
#define OD 2048
#define NR (BT*LD)
#define NE (NR*CD)

#define MODE_NONE 0
#define MODE_ZRH  1
#define MODE_GRU2 2
#define MODE_TANH 3

#define TM 64
#define NOMASK 0x7FFFFFFF

// ---------------- fp32 scratch ----------------
__device__ float d_fwd[LD*CD];
__device__ float d_v[CD];
__device__ float d_c0p[CD];
__device__ float d_ball[3*CD];
__device__ float d_fwh[NP*CD];
__device__ float d_coeff[NP*LD];
__device__ float d_nodes[NE];
__device__ float d_zbuf[NE];
__device__ float d_hbuf[NE];

// ---------------- bf16 hi/lo operand buffers ----------------
__device__ unsigned short c_img_h[NP*CD],    c_img_l[NP*CD];
__device__ unsigned short c_fc1_h[CD*CD],    c_fc1_l[CD*CD];
__device__ unsigned short c_wemb_h[LD*WPAD], c_wemb_l[LD*WPAD];
__device__ unsigned short c_fc2_h[CD*WPAD],  c_fc2_l[CD*WPAD];
__device__ unsigned short c_wall_h[3*CD*CD], c_wall_l[3*CD*CD];
__device__ unsigned short c_u3_h[CD*CD],     c_u3_l[CD*CD];
__device__ unsigned short c_u5_h[CD*CD],     c_u5_l[CD*CD];
__device__ unsigned short c_fco_h[OD*2*CD],  c_fco_l[OD*2*CD];
__device__ unsigned short c_nodes_h[NE],     c_nodes_l[NE];
__device__ unsigned short c_a_h[NE],         c_a_l[NE];
__device__ unsigned short c_rn_h[NE],        c_rn_l[NE];
__device__ unsigned short c_g_h[NE],         c_g_l[NE];

// ---------------- helpers ----------------
__device__ __forceinline__ uint32_t smem_to_u32(const void* p) {
    uint32_t a;
    asm("{ .reg .u64 t; cvta.to.shared.u64 t, %1; cvt.u32.u64 %0, t; }" : "=r"(a) : "l"(p));
    return a;
}
__device__ __forceinline__ void split_bf(float v, unsigned short* h, unsigned short* l) {
    __nv_bfloat16 hb = __float2bfloat16(v);
    *h = __bfloat16_as_ushort(hb);
    *l = __bfloat16_as_ushort(__float2bfloat16(v - __bfloat162float(hb)));
}
__device__ __forceinline__ void ldsm_x4(uint32_t* r, uint32_t addr) {
    asm volatile("ldmatrix.sync.aligned.m8n8.x4.shared.b16 {%0,%1,%2,%3}, [%4];"
        : "=r"(r[0]), "=r"(r[1]), "=r"(r[2]), "=r"(r[3]) : "r"(addr));
}
__device__ __forceinline__ void mma16816(float* c, const uint32_t* a, const uint32_t* b) {
    asm volatile("mma.sync.aligned.m16n8k16.row.col.f32.bf16.bf16.f32 "
        "{%0,%1,%2,%3}, {%4,%5,%6,%7}, {%8,%9}, {%0,%1,%2,%3};"
        : "+f"(c[0]), "+f"(c[1]), "+f"(c[2]), "+f"(c[3])
        : "r"(a[0]), "r"(a[1]), "r"(a[2]), "r"(a[3]), "r"(b[0]), "r"(b[1]));
}
__device__ __forceinline__ void cpasync16(uint32_t dst, const void* src, bool ok) {
    asm volatile("cp.async.cg.shared.global [%0], [%1], 16, %2;"
        :: "r"(dst), "l"(src), "r"(ok ? 16 : 0) : "memory");
}
__device__ __forceinline__ void cp_commit() {
    asm volatile("cp.async.commit_group;" ::: "memory");
}
template<int N> __device__ __forceinline__ void cp_waitN() {
    asm volatile("cp.async.wait_group %0;" :: "n"(N) : "memory");
}
__device__ __forceinline__ uint32_t sw64(uint32_t off) {
    return off ^ ((off >> 3) & 0x30);
}

// ---------------- merged prep: converts + wsum + bias + v + c0 partials --------------
__global__ void k_prep(const float* __restrict__ fc1, const float* __restrict__ img,
                       const float* __restrict__ wemb, const float* __restrict__ fc2,
                       const float* __restrict__ u3, const float* __restrict__ u5,
                       const float* __restrict__ fco,
                       const float* __restrict__ w3, const float* __restrict__ w4,
                       const float* __restrict__ w5,
                       const float* __restrict__ b3, const float* __restrict__ u3b,
                       const float* __restrict__ b4, const float* __restrict__ b5,
                       const float* __restrict__ u5b,
                       const float* __restrict__ fc3, const float* __restrict__ fca,
                       const float* __restrict__ fc3b) {
    const int o1 = CD*CD;                 // fc1
    const int o2 = o1 + NP*CD;            // img
    const int o3 = o2 + LD*WPAD;          // wemb (padded)
    const int o4 = o3 + CD*WPAD;          // fc2  (padded)
    const int o5 = o4 + CD*CD;            // u3
    const int o6 = o5 + CD*CD;            // u5
    const int o7 = o6 + OD*2*CD;          // fco
    const int o8 = o7 + 3*CD*CD;          // wsum
    const int o9 = o8 + 3*CD;             // bias
    const int o10 = o9 + CD;              // v
    const int o11 = o10 + CD;             // c0 partials
    int stride = gridDim.x * blockDim.x;
    for (int i = blockIdx.x*blockDim.x + threadIdx.x; i < o11; i += stride) {
        if (i < o1) {
            split_bf(fc1[i], &c_fc1_h[i], &c_fc1_l[i]);
        } else if (i < o2) {
            int j = i - o1;
            split_bf(img[j], &c_img_h[j], &c_img_l[j]);
        } else if (i < o3) {
            int j = i - o2, r = j / WPAD, c = j - r*WPAD;
            float v = (c < WDIM) ? wemb[r*WDIM + c] : 0.f;
            split_bf(v, &c_wemb_h[j], &c_wemb_l[j]);
        } else if (i < o4) {
            int j = i - o3, r = j / WPAD, c = j - r*WPAD;
            float v = (c < WDIM) ? fc2[r*WDIM + c] : 0.f;
            split_bf(v, &c_fc2_h[j], &c_fc2_l[j]);
        } else if (i < o5) {
            int j = i - o4;
            split_bf(u3[j], &c_u3_h[j], &c_u3_l[j]);
        } else if (i < o6) {
            int j = i - o5;
            split_bf(u5[j], &c_u5_h[j], &c_u5_l[j]);
        } else if (i < o7) {
            int j = i - o6;
            split_bf(fco[j], &c_fco_h[j], &c_fco_l[j]);
        } else if (i < o8) {
            int j = i - o7;
            int which = j / (CD*CD);
            int rem = j - which*(CD*CD);
            int r = rem >> 10, c = rem & (CD-1);
            const float* w = (which==0) ? w3 : (which==1) ? w4 : w5;
            float val = w[r*2*CD + c] + w[r*2*CD + CD + c];
            split_bf(val, &c_wall_h[j], &c_wall_l[j]);
        } else if (i < o9) {
            int j = i - o8;
            int which = j >> 10, c = j & (CD-1);
            if (which == 0)      d_ball[c]        = b3[c] + u3b[c];
            else if (which == 1) d_ball[CD + c]   = b4[c] + u3b[c]; // torch bug kept
            else                 d_ball[2*CD + c] = b5[c] + u5b[c];
        } else if (i < o10) {
            int c = i - o9;                 // v[c] = sum_j fca[j]*fc3[j,c]
            float acc = 0.f;
            #pragma unroll 8
            for (int j = 0; j < CD; ++j) acc += fca[j] * fc3[j*CD + c];
            d_v[c] = acc;
        } else {
            int j = i - o10;                // c0 partial
            d_c0p[j] = fc3b[j] * fca[j];
        }
    }
}

// ---------------- tensor GEMM: templated tile-N, 3-stage cp.async ring ---------------
// C = epi( A@B^T [+ A2@B2^T] + bias ); fp32 via bf16 split (hh + hl + lh).
template<int MODE, int TNN>
__global__ __launch_bounds__(128) void t_gemm(
    const unsigned short* __restrict__ Ah, const unsigned short* __restrict__ Al, int lda,
    const unsigned short* __restrict__ Bh, const unsigned short* __restrict__ Bl, int ldb,
    const unsigned short* __restrict__ A2h, const unsigned short* __restrict__ A2l, int lda2,
    const unsigned short* __restrict__ B2h, const unsigned short* __restrict__ B2l, int ldb2,
    int b2mask, int n2_limit,
    int M, int N, int Kpad,
    const float* __restrict__ bias,
    float* __restrict__ p0, float* __restrict__ p1, float* __restrict__ p2,
    unsigned short* __restrict__ q0, unsigned short* __restrict__ q1,
    float* __restrict__ C, int ldc)
{
    constexpr int JF = TNN/16;            // B col-frags per warp (warp n-span = 8*JF)
    constexpr int JH = JF/2;              // B ldsm_x4 pairs per warp
    constexpr int STAGE = 8192 + TNN*128; // A hi/lo 8K + B hi/lo TNN*128
    constexpr int BCOPY = TNN*4;          // 16B copies per B half
    __shared__ __align__(128) char dsm[3*STAGE];
    uint32_t sbase = smem_to_u32(dsm);

    const int tid = threadIdx.x;
    const int wid = tid >> 5;
    const int lane = tid & 31;
    const int m0 = blockIdx.y * TM;
    const int n0 = blockIdx.x * TNN;
    const int wm = (wid >> 1) * 32;
    const int wn = (wid & 1) * (TNN/2);

    const int qm = lane >> 3, rr = lane & 7;
    const int lrow = (qm & 1)*8 + rr;
    const int lkof = (qm >> 1)*8;

    float acc[2][JF][4];
    #pragma unroll
    for (int i = 0; i < 2; ++i)
        #pragma unroll
        for (int j = 0; j < JF; ++j)
            #pragma unroll
            for (int s = 0; s < 4; ++s) acc[i][j][s] = 0.f;

    const int nst1 = Kpad >> 5;
    const bool do2 = (A2h != nullptr) && (n0 < n2_limit);
    const int nst = do2 ? 2*nst1 : nst1;

    auto stage = [&](int t) {
        int pass = (t >= nst1) ? 1 : 0;
        int k0 = (t - pass*nst1) << 5;
        const unsigned short* pAh = pass ? A2h : Ah;
        const unsigned short* pAl = pass ? A2l : Al;
        const unsigned short* pBh = pass ? B2h : Bh;
        const unsigned short* pBl = pass ? B2l : Bl;
        int la = pass ? lda2 : lda;
        int lb = pass ? ldb2 : ldb;
        int bm = pass ? b2mask : NOMASK;
        uint32_t sb = sbase + (t % 3) * STAGE;
        #pragma unroll
        for (int qq = 0; qq*128 < 512 + 2*BCOPY; ++qq) {
            int c = tid + (qq << 7);
            if (c < 512) {             // A: hi [0,256) lo [256,512)
                int part = c >> 8;
                int sub = c & 255;
                int row = sub >> 2, quad = sub & 3;
                int gr = m0 + row;
                bool ok = gr < M;
                const unsigned short* s = (part ? pAl : pAh)
                                          + (size_t)(ok ? gr : 0)*la + k0 + quad*8;
                uint32_t off = sw64((uint32_t)(row*64 + quad*16));
                cpasync16(sb + part*4096 + off, s, ok);
            } else {                   // B: hi then lo, BCOPY each
                int cb = c - 512;
                int part = (cb >= BCOPY) ? 1 : 0;
                int sub = cb - part*BCOPY;
                int row = sub >> 2, quad = sub & 3;
                int gn = n0 + row;
                bool ok = gn < N;
                int er = (ok ? gn : 0) & bm;
                const unsigned short* s = (part ? pBl : pBh)
                                          + (size_t)er*lb + k0 + quad*8;
                uint32_t off = sw64((uint32_t)(row*64 + quad*16));
                cpasync16(sb + 8192 + part*(TNN*64) + off, s, ok);
            }
        }
        cp_commit();
    };

    stage(0);
    if (nst > 1) stage(1);
    for (int t = 0; t < nst; ++t) {
        if (t + 2 < nst) { stage(t + 2); cp_waitN<2>(); }
        else if (t + 1 < nst) cp_waitN<1>();
        else cp_waitN<0>();
        __syncthreads();
        uint32_t sb = sbase + (t % 3) * STAGE;
        uint32_t sa_hi = sb, sa_lo = sb + 4096;
        uint32_t sb_hi = sb + 8192, sb_lo = sb + 8192 + TNN*64;
        #pragma unroll
        for (int k0 = 0; k0 < 32; k0 += 16) {
            uint32_t ah[2][4], al[2][4], bh[JF][2], bl[JF][2];
            #pragma unroll
            for (int i = 0; i < 2; ++i) {
                uint32_t off = sw64((uint32_t)((wm + i*16 + lrow)*64 + (k0 + lkof)*2));
                ldsm_x4(ah[i], sa_hi + off);
                ldsm_x4(al[i], sa_lo + off);
            }
            #pragma unroll
            for (int jh = 0; jh < JH; ++jh) {
                uint32_t off = sw64((uint32_t)((wn + jh*16 + lrow)*64 + (k0 + lkof)*2));
                uint32_t r[4];
                ldsm_x4(r, sb_hi + off);
                bh[2*jh][0]=r[0]; bh[2*jh][1]=r[2]; bh[2*jh+1][0]=r[1]; bh[2*jh+1][1]=r[3];
                ldsm_x4(r, sb_lo + off);
                bl[2*jh][0]=r[0]; bl[2*jh][1]=r[2]; bl[2*jh+1][0]=r[1]; bl[2*jh+1][1]=r[3];
            }
            #pragma unroll
            for (int i = 0; i < 2; ++i)
                #pragma unroll
                for (int j = 0; j < JF; ++j) {
                    mma16816(acc[i][j], ah[i], bh[j]);
                    mma16816(acc[i][j], ah[i], bl[j]);
                    mma16816(acc[i][j], al[i], bh[j]);
                }
        }
        __syncthreads();
    }

    // epilogue
    const int g = lane >> 2, tq = (lane & 3)*2;
    #pragma unroll
    for (int i = 0; i < 2; ++i) {
        #pragma unroll
        for (int half = 0; half < 2; ++half) {
            int m = m0 + wm + i*16 + g + half*8;
            if (m >= M) continue;
            #pragma unroll
            for (int j = 0; j < JF; ++j) {
                #pragma unroll
                for (int s = 0; s < 2; ++s) {
                    int n = n0 + wn + j*8 + tq + s;
                    if (n >= N) continue;
                    float x = acc[i][j][half*2 + s];
                    if (MODE == MODE_NONE) {
                        C[(size_t)m*ldc + n] = x;
                    } else if (MODE == MODE_ZRH) {
                        x += bias[n];
                        if (n < CD) {
                            p0[m*CD + n] = 1.f/(1.f + expf(-x));
                        } else if (n < 2*CD) {
                            int nn = n - CD;
                            float rn = (1.f/(1.f + expf(-x))) * p2[m*CD + nn];
                            split_bf(rn, &q0[m*CD + nn], &q1[m*CD + nn]);
                        } else {
                            p1[m*CD + (n - 2*CD)] = x;
                        }
                    } else if (MODE == MODE_GRU2) {
                        float hc = tanhf(x + p1[m*CD + n]);
                        float z  = p0[m*CD + n];
                        float nv = (1.f - z)*p2[m*CD + n] + z*hc;
                        p2[m*CD + n] = nv;
                        split_bf(nv, &q0[m*CD + n], &q1[m*CD + n]);
                    } else { // MODE_TANH
                        C[(size_t)m*ldc + n] = tanhf(x + bias[n]);
                    }
                }
            }
        }
    }
}

// ---------------- semantic-branch kernels ----------------
// register-cached coeff: per lane keep fwh[n, 32q+lane] and v[32q+lane] in regs
__global__ __launch_bounds__(256) void k_coeff(const float* __restrict__ fcab) {
    int n = blockIdx.x;
    int warp = threadIdx.x >> 5, lane = threadIdx.x & 31;
    float fw_r[32], v_r[32];
    const float* fwhrow = d_fwh + n*CD + lane;
    #pragma unroll
    for (int q = 0; q < 32; ++q) {
        fw_r[q] = fwhrow[q*32];
        v_r[q]  = d_v[q*32 + lane];
    }
    float c0 = 0.f;
    #pragma unroll
    for (int q = 0; q < 32; ++q) c0 += d_c0p[q*32 + lane];
    #pragma unroll
    for (int o = 16; o > 0; o >>= 1) c0 += __shfl_xor_sync(0xffffffffu, c0, o);
    c0 += fcab[0];
    for (int l = warp; l < LD; l += 8) {
        const float* fw = d_fwd + l*CD + lane;
        float acc = 0.f;
        #pragma unroll
        for (int q = 0; q < 32; ++q) {
            float p = fw_r[q] * fw[q*32];
            float tv;
            asm("tanh.approx.f32 %0, %1;" : "=f"(tv) : "f"(p));
            acc += tv * v_r[q];
        }
        #pragma unroll
        for (int o = 16; o > 0; o >>= 1) acc += __shfl_xor_sync(0xffffffffu, acc, o);
        if (lane == 0) d_coeff[n*LD + l] = acc + c0;
    }
}

__global__ __launch_bounds__(256) void k_softmax() {
    int g = blockIdx.x*8 + (threadIdx.x >> 5);
    int lane = threadIdx.x & 31;
    if (g >= NP*LD/HW) return;
    float* p = d_coeff + g*HW;
    float vals[7];
    float mx = -1e30f;
    #pragma unroll
    for (int q = 0; q < 7; ++q) {
        int i = lane + q*32;
        vals[q] = (i < HW) ? p[i] : -1e30f;
        mx = fmaxf(mx, vals[q]);
    }
    #pragma unroll
    for (int o = 16; o > 0; o >>= 1) mx = fmaxf(mx, __shfl_xor_sync(0xffffffffu, mx, o));
    float s = 0.f;
    #pragma unroll
    for (int q = 0; q < 7; ++q) {
        int i = lane + q*32;
        if (i < HW) { vals[q] = expf(vals[q] - mx); s += vals[q]; }
    }
    #pragma unroll
    for (int o = 16; o > 0; o >>= 1) s += __shfl_xor_sync(0xffffffffu, s, o);
    float inv = 1.f / s;
    #pragma unroll
    for (int q = 0; q < 7; ++q) {
        int i = lane + q*32;
        if (i < HW) p[i] = vals[q]*inv;
    }
}

__global__ __launch_bounds__(256) void k_g(const float* __restrict__ img) {
    __shared__ float s[HW];
    int b = blockIdx.x / LD, l = blockIdx.x % LD;
    for (int tt = threadIdx.x; tt < HW; tt += 256)
        s[tt] = d_coeff[(b*HW + tt)*LD + l];
    __syncthreads();
    const float* xb = img + b*HW*CD;
    int c = threadIdx.x;
    float a0 = 0.f, a1 = 0.f, a2 = 0.f, a3 = 0.f;
    #pragma unroll 4
    for (int tt = 0; tt < HW; ++tt) {
        float w = s[tt];
        const float* xr = xb + tt*CD;
        a0 += w*xr[c]; a1 += w*xr[c+256]; a2 += w*xr[c+512]; a3 += w*xr[c+768];
    }
    int base = (b*LD + l)*CD + c;
    float vals[4] = {a0, a1, a2, a3};
    #pragma unroll
    for (int q = 0; q < 4; ++q) {
        int idx = base + q*256;
        d_nodes[idx] = vals[q];
        split_bf(vals[q], &c_g_h[idx], &c_g_l[idx]);
        c_nodes_h[idx] = c_g_h[idx];
        c_nodes_l[idx] = c_g_l[idx];
    }
}

__global__ __launch_bounds__(256) void k_a(const float* __restrict__ adj) {
    __shared__ float ar[LD];
    int b = blockIdx.x / LD, nn = blockIdx.x % LD;
    if (threadIdx.x < LD) ar[threadIdx.x] = adj[nn*LD + threadIdx.x];
    __syncthreads();
    int c = threadIdx.x;
    const float* nb = d_nodes + b*LD*CD;
    float a0 = 0.f, a1 = 0.f, a2 = 0.f, a3 = 0.f;
    #pragma unroll 4
    for (int m = 0; m < LD; ++m) {
        float w = ar[m];
        const float* nr = nb + m*CD;
        a0 += w*nr[c]; a1 += w*nr[c+256]; a2 += w*nr[c+512]; a3 += w*nr[c+768];
    }
    int base = (b*LD + nn)*CD + c;
    float vals[4] = {a0, a1, a2, a3};
    #pragma unroll
    for (int q = 0; q < 4; ++q) {
        int idx = base + q*256;
        split_bf(vals[q], &c_a_h[idx], &c_a_l[idx]);
    }
}

// ---------------- host ----------------
struct Sym {
    float *fwd, *v, *c0p, *ball, *fwh, *coeff, *nodes, *zbuf, *hbuf;
    unsigned short *imgh, *imgl, *fc1h, *fc1l, *wembh, *wembl, *fc2h, *fc2l;
    unsigned short *wallh, *walll, *u3h, *u3l, *u5h, *u5l, *fcoh, *fcol;
    unsigned short *ndh, *ndl, *ah, *al, *rnh, *rnl, *gh, *gl;
};
static void get_syms(Sym& S) {
    cudaGetSymbolAddress((void**)&S.fwd, d_fwd);
    cudaGetSymbolAddress((void**)&S.v, d_v);
    cudaGetSymbolAddress((void**)&S.c0p, d_c0p);
    cudaGetSymbolAddress((void**)&S.ball, d_ball);
    cudaGetSymbolAddress((void**)&S.fwh, d_fwh);
    cudaGetSymbolAddress((void**)&S.coeff, d_coeff);
    cudaGetSymbolAddress((void**)&S.nodes, d_nodes);
    cudaGetSymbolAddress((void**)&S.zbuf, d_zbuf);
    cudaGetSymbolAddress((void**)&S.hbuf, d_hbuf);
    cudaGetSymbolAddress((void**)&S.imgh, c_img_h);   cudaGetSymbolAddress((void**)&S.imgl, c_img_l);
    cudaGetSymbolAddress((void**)&S.fc1h, c_fc1_h);   cudaGetSymbolAddress((void**)&S.fc1l, c_fc1_l);
    cudaGetSymbolAddress((void**)&S.wembh, c_wemb_h); cudaGetSymbolAddress((void**)&S.wembl, c_wemb_l);
    cudaGetSymbolAddress((void**)&S.fc2h, c_fc2_h);   cudaGetSymbolAddress((void**)&S.fc2l, c_fc2_l);
    cudaGetSymbolAddress((void**)&S.wallh, c_wall_h); cudaGetSymbolAddress((void**)&S.walll, c_wall_l);
    cudaGetSymbolAddress((void**)&S.u3h, c_u3_h);     cudaGetSymbolAddress((void**)&S.u3l, c_u3_l);
    cudaGetSymbolAddress((void**)&S.u5h, c_u5_h);     cudaGetSymbolAddress((void**)&S.u5l, c_u5_l);
    cudaGetSymbolAddress((void**)&S.fcoh, c_fco_h);   cudaGetSymbolAddress((void**)&S.fcol, c_fco_l);
    cudaGetSymbolAddress((void**)&S.ndh, c_nodes_h);  cudaGetSymbolAddress((void**)&S.ndl, c_nodes_l);
    cudaGetSymbolAddress((void**)&S.ah, c_a_h);       cudaGetSymbolAddress((void**)&S.al, c_a_l);
    cudaGetSymbolAddress((void**)&S.rnh, c_rn_h);     cudaGetSymbolAddress((void**)&S.rnl, c_rn_l);
    cudaGetSymbolAddress((void**)&S.gh, c_g_h);       cudaGetSymbolAddress((void**)&S.gl, c_g_l);
}

template<int MODE, int TNN>
static void tg(const unsigned short* Ah, const unsigned short* Al, int lda,
               const unsigned short* Bh, const unsigned short* Bl, int ldb,
               const unsigned short* A2h, const unsigned short* A2l, int lda2,
               const unsigned short* B2h, const unsigned short* B2l, int ldb2,
               int b2mask, int n2lim, int M, int N, int Kpad,
               const float* bias, float* p0, float* p1, float* p2,
               unsigned short* q0, unsigned short* q1, float* C, int ldc) {
    dim3 grid((N + TNN - 1)/TNN, (M + TM - 1)/TM);
    t_gemm<MODE, TNN><<<grid, 128>>>(Ah, Al, lda, Bh, Bl, ldb, A2h, A2l, lda2,
                                     B2h, B2l, ldb2, b2mask, n2lim, M, N, Kpad,
                                     bias, p0, p1, p2, q0, q1, C, ldc);
}

extern "C" void kernel_launch(void* const* d_in, const int* in_sizes, int n_in,
                              void* d_out, int out_size) {
    const float* img  = (const float*)d_in[0];
    const float* wemb = (const float*)d_in[1];
    const float* adj  = (const float*)d_in[2];
    const float* fc1  = (const float*)d_in[3];
    const float* fc2  = (const float*)d_in[4];
    const float* fc3  = (const float*)d_in[5];
    const float* fc3b = (const float*)d_in[6];
    const float* fca  = (const float*)d_in[7];
    const float* fcab = (const float*)d_in[8];
    const float* w3   = (const float*)d_in[9];
    const float* b3   = (const float*)d_in[10];
    const float* u3   = (const float*)d_in[11];
    const float* u3b  = (const float*)d_in[12];
    const float* w4   = (const float*)d_in[13];
    const float* b4   = (const float*)d_in[14];
    const float* w5   = (const float*)d_in[15];
    const float* b5   = (const float*)d_in[16];
    const float* u5   = (const float*)d_in[17];
    const float* u5b  = (const float*)d_in[18];
    const float* fco  = (const float*)d_in[19];
    const float* fcob = (const float*)d_in[20];
    float* out = (float*)d_out;

    Sym S; get_syms(S);

    // 1: converts + wsum + bias + v + c0 partials
    k_prep<<<2048, 256>>>(fc1, img, wemb, fc2, u3, u5, fco,
                          w3, w4, w5, b3, u3b, b4, b5, u5b,
                          fc3, fca, fc3b);
    // 2: f_wh = x @ fc1^T
    tg<MODE_NONE, 32>(S.imgh, S.imgl, CD, S.fc1h, S.fc1l, CD,
                      nullptr, nullptr, 0, nullptr, nullptr, 0, NOMASK, 0,
                      NP, CD, CD, nullptr, nullptr, nullptr, nullptr, nullptr, nullptr,
                      S.fwh, CD);
    // 3: f_wd = wemb @ fc2^T
    tg<MODE_NONE, 32>(S.wembh, S.wembl, WPAD, S.fc2h, S.fc2l, WPAD,
                      nullptr, nullptr, 0, nullptr, nullptr, 0, NOMASK, 0,
                      LD, CD, WPAD, nullptr, nullptr, nullptr, nullptr, nullptr, nullptr,
                      S.fwd, CD);
    // 4: k_coeff  (ncu capture slot)
    k_coeff<<<NP, 256>>>(fcab);
    // 5-6
    k_softmax<<<40, 256>>>();
    k_g<<<BT*LD, 256>>>(img);

    // GGNN
    for (int step = 0; step < 3; ++step) {
        k_a<<<BT*LD, 256>>>(adj);
        tg<MODE_ZRH, 32>(S.ah, S.al, CD, S.wallh, S.walll, CD,
                         S.ndh, S.ndl, CD, S.u3h, S.u3l, CD, CD-1, 2*CD,
                         NR, 3*CD, CD, S.ball, S.zbuf, S.hbuf, S.nodes,
                         S.rnh, S.rnl, nullptr, 0);
        tg<MODE_GRU2, 32>(S.rnh, S.rnl, CD, S.u5h, S.u5l, CD,
                          nullptr, nullptr, 0, nullptr, nullptr, 0, NOMASK, 0,
                          NR, CD, CD, nullptr, S.zbuf, S.hbuf, S.nodes,
                          S.ndh, S.ndl, nullptr, 0);
    }

    // out = tanh([nodes, g] @ fco^T + fco_b): dual-K over fco column halves
    tg<MODE_TANH, 32>(S.ndh, S.ndl, CD, S.fcoh, S.fcol, 2*CD,
                      S.gh, S.gl, CD, S.fcoh + CD, S.fcol + CD, 2*CD, NOMASK, NOMASK,
                      NR, OD, CD, fcob, nullptr, nullptr, nullptr, nullptr, nullptr,
                      out, OD);
}

// round 12
// speedup vs baseline: 2.8011x; 1.0615x over previous
#include <cuda_runtime.h>
#include <cuda_bf16.h>
#include <math.h>
#include <stdint.h>

#define CD 1024
#define LD 80
#define WDIM 300
#define WPAD 320
#define HW 196
#define BT 4
#define NP 784
#define OD 2048
#define NR (BT*LD)
#define NE (NR*CD)

#define MODE_NONE 0
#define MODE_ZRH  1
#define MODE_GRU2 2
#define MODE_TANH 3

#define TM 64
#define NOMASK 0x7FFFFFFF

// ---------------- fp32 scratch ----------------
__device__ float d_fwd[LD*CD];
__device__ float d_v[CD];
__device__ float d_c0p[CD];
__device__ float d_ball[3*CD];
__device__ float d_fwh[NP*CD];
__device__ float d_coeff[NP*LD];
__device__ float d_nodes[NE];
__device__ float d_zbuf[NE];
__device__ float d_hbuf[NE];

// ---------------- bf16 hi/lo operand buffers ----------------
__device__ unsigned short c_img_h[NP*CD],    c_img_l[NP*CD];
__device__ unsigned short c_fc1_h[CD*CD],    c_fc1_l[CD*CD];
__device__ unsigned short c_wemb_h[LD*WPAD], c_wemb_l[LD*WPAD];
__device__ unsigned short c_fc2_h[CD*WPAD],  c_fc2_l[CD*WPAD];
__device__ unsigned short c_wall_h[3*CD*CD], c_wall_l[3*CD*CD];
__device__ unsigned short c_u3_h[CD*CD],     c_u3_l[CD*CD];
__device__ unsigned short c_u5_h[CD*CD],     c_u5_l[CD*CD];
__device__ unsigned short c_fco_h[OD*2*CD],  c_fco_l[OD*2*CD];
__device__ unsigned short c_nodes_h[NE],     c_nodes_l[NE];
__device__ unsigned short c_a_h[NE],         c_a_l[NE];
__device__ unsigned short c_rn_h[NE],        c_rn_l[NE];
__device__ unsigned short c_g_h[NE],         c_g_l[NE];

// ---------------- helpers ----------------
__device__ __forceinline__ uint32_t smem_to_u32(const void* p) {
    uint32_t a;
    asm("{ .reg .u64 t; cvta.to.shared.u64 t, %1; cvt.u32.u64 %0, t; }" : "=r"(a) : "l"(p));
    return a;
}
__device__ __forceinline__ void split_bf(float v, unsigned short* h, unsigned short* l) {
    __nv_bfloat16 hb = __float2bfloat16(v);
    *h = __bfloat16_as_ushort(hb);
    *l = __bfloat16_as_ushort(__float2bfloat16(v - __bfloat162float(hb)));
}
// pair split: two elements -> packed uint32 hi-pair + lo-pair (halves store count)
__device__ __forceinline__ void split2(float x, float y,
                                       unsigned short* hbase, unsigned short* lbase, int e) {
    __nv_bfloat16 h0 = __float2bfloat16(x), h1 = __float2bfloat16(y);
    float l0 = x - __bfloat162float(h0), l1 = y - __bfloat162float(h1);
    uint32_t hp = (uint32_t)__bfloat16_as_ushort(h0) |
                  ((uint32_t)__bfloat16_as_ushort(h1) << 16);
    uint32_t lp = (uint32_t)__bfloat16_as_ushort(__float2bfloat16(l0)) |
                  ((uint32_t)__bfloat16_as_ushort(__float2bfloat16(l1)) << 16);
    *(uint32_t*)&hbase[e] = hp;
    *(uint32_t*)&lbase[e] = lp;
}
__device__ __forceinline__ void ldsm_x4(uint32_t* r, uint32_t addr) {
    asm volatile("ldmatrix.sync.aligned.m8n8.x4.shared.b16 {%0,%1,%2,%3}, [%4];"
        : "=r"(r[0]), "=r"(r[1]), "=r"(r[2]), "=r"(r[3]) : "r"(addr));
}
__device__ __forceinline__ void mma16816(float* c, const uint32_t* a, const uint32_t* b) {
    asm volatile("mma.sync.aligned.m16n8k16.row.col.f32.bf16.bf16.f32 "
        "{%0,%1,%2,%3}, {%4,%5,%6,%7}, {%8,%9}, {%0,%1,%2,%3};"
        : "+f"(c[0]), "+f"(c[1]), "+f"(c[2]), "+f"(c[3])
        : "r"(a[0]), "r"(a[1]), "r"(a[2]), "r"(a[3]), "r"(b[0]), "r"(b[1]));
}
__device__ __forceinline__ void cpasync16(uint32_t dst, const void* src, bool ok) {
    asm volatile("cp.async.cg.shared.global [%0], [%1], 16, %2;"
        :: "r"(dst), "l"(src), "r"(ok ? 16 : 0) : "memory");
}
__device__ __forceinline__ void cp_commit() {
    asm volatile("cp.async.commit_group;" ::: "memory");
}
template<int N> __device__ __forceinline__ void cp_waitN() {
    asm volatile("cp.async.wait_group %0;" :: "n"(N) : "memory");
}
__device__ __forceinline__ uint32_t sw64(uint32_t off) {
    return off ^ ((off >> 3) & 0x30);
}

// ---------------- prep A: semantic operands (fc1, img, wemb, fc2), pair-vectorized ----
__global__ void k_prepA(const float* __restrict__ fc1, const float* __restrict__ img,
                        const float* __restrict__ wemb, const float* __restrict__ fc2) {
    const int p1 = CD*CD/2;
    const int p2 = p1 + NP*CD/2;
    const int p3 = p2 + LD*WPAD/2;
    const int p4 = p3 + CD*WPAD/2;
    int stride = gridDim.x*blockDim.x;
    for (int i = blockIdx.x*blockDim.x + threadIdx.x; i < p4; i += stride) {
        if (i < p1) {
            int e = 2*i;
            float2 v = *(const float2*)&fc1[e];
            split2(v.x, v.y, c_fc1_h, c_fc1_l, e);
        } else if (i < p2) {
            int e = 2*(i - p1);
            float2 v = *(const float2*)&img[e];
            split2(v.x, v.y, c_img_h, c_img_l, e);
        } else if (i < p3) {
            int e = 2*(i - p2);
            int r = e / WPAD, c = e - r*WPAD;
            float2 v = (c < WDIM) ? *(const float2*)&wemb[r*WDIM + c]
                                  : make_float2(0.f, 0.f);
            split2(v.x, v.y, c_wemb_h, c_wemb_l, e);
        } else {
            int e = 2*(i - p3);
            int r = e / WPAD, c = e - r*WPAD;
            float2 v = (c < WDIM) ? *(const float2*)&fc2[r*WDIM + c]
                                  : make_float2(0.f, 0.f);
            split2(v.x, v.y, c_fc2_h, c_fc2_l, e);
        }
    }
}

// ---------------- prep B: GGNN operands + biases + v + c0 partials -------------------
__global__ void k_prepB(const float* __restrict__ u3, const float* __restrict__ u5,
                        const float* __restrict__ fco,
                        const float* __restrict__ w3, const float* __restrict__ w4,
                        const float* __restrict__ w5,
                        const float* __restrict__ b3, const float* __restrict__ u3b,
                        const float* __restrict__ b4, const float* __restrict__ b5,
                        const float* __restrict__ u5b,
                        const float* __restrict__ fc3, const float* __restrict__ fca,
                        const float* __restrict__ fc3b) {
    const int p1 = CD*CD/2;                 // u3
    const int p2 = p1 + CD*CD/2;            // u5
    const int p3 = p2 + OD*2*CD/2;          // fco
    const int p4 = p3 + 3*CD*CD/2;          // wall (summed)
    const int p5 = p4 + 3*CD;               // bias
    const int p6 = p5 + CD;                 // v
    const int p7 = p6 + CD;                 // c0 partials
    int stride = gridDim.x*blockDim.x;
    for (int i = blockIdx.x*blockDim.x + threadIdx.x; i < p7; i += stride) {
        if (i < p1) {
            int e = 2*i;
            float2 v = *(const float2*)&u3[e];
            split2(v.x, v.y, c_u3_h, c_u3_l, e);
        } else if (i < p2) {
            int e = 2*(i - p1);
            float2 v = *(const float2*)&u5[e];
            split2(v.x, v.y, c_u5_h, c_u5_l, e);
        } else if (i < p3) {
            int e = 2*(i - p2);
            float2 v = *(const float2*)&fco[e];
            split2(v.x, v.y, c_fco_h, c_fco_l, e);
        } else if (i < p4) {
            int e = 2*(i - p3);
            int which = e / (CD*CD);
            int rem = e - which*(CD*CD);
            int r = rem >> 10, c = rem & (CD-1);
            const float* w = (which==0) ? w3 : (which==1) ? w4 : w5;
            float2 a = *(const float2*)&w[r*2*CD + c];
            float2 b = *(const float2*)&w[r*2*CD + CD + c];
            split2(a.x + b.x, a.y + b.y, c_wall_h, c_wall_l, e);
        } else if (i < p5) {
            int j = i - p4;
            int which = j >> 10, c = j & (CD-1);
            if (which == 0)      d_ball[c]        = b3[c] + u3b[c];
            else if (which == 1) d_ball[CD + c]   = b4[c] + u3b[c]; // torch bug kept
            else                 d_ball[2*CD + c] = b5[c] + u5b[c];
        } else if (i < p6) {
            int c = i - p5;                 // v[c] = sum_j fca[j]*fc3[j,c]
            float acc = 0.f;
            #pragma unroll 8
            for (int j = 0; j < CD; ++j) acc += fca[j] * fc3[j*CD + c];
            d_v[c] = acc;
        } else {
            int j = i - p6;                 // c0 partial
            d_c0p[j] = fc3b[j] * fca[j];
        }
    }
}

// ---------------- tensor GEMM: 4-stage cp.async ring, ONE barrier per stage ----------
// C = epi( A@B^T [+ A2@B2^T] + bias ); fp32 via bf16 split (hh + hl + lh).
// Ring safety: per iter = wait<2> -> barrier -> compute(t) -> stage(t+3).
// stage(t+3) writes buf (t+3)%4 == (t-1)%4; all warps past barrier-t finished
// compute(t-1), so no overwrite. Each thread's wait<2> drains its own group t
// before the barrier publishes all threads' copies.
template<int MODE, int TNN>
__global__ __launch_bounds__(128) void t_gemm(
    const unsigned short* __restrict__ Ah, const unsigned short* __restrict__ Al, int lda,
    const unsigned short* __restrict__ Bh, const unsigned short* __restrict__ Bl, int ldb,
    const unsigned short* __restrict__ A2h, const unsigned short* __restrict__ A2l, int lda2,
    const unsigned short* __restrict__ B2h, const unsigned short* __restrict__ B2l, int ldb2,
    int b2mask, int n2_limit,
    int M, int N, int Kpad,
    const float* __restrict__ bias,
    float* __restrict__ p0, float* __restrict__ p1, float* __restrict__ p2,
    unsigned short* __restrict__ q0, unsigned short* __restrict__ q1,
    float* __restrict__ C, int ldc)
{
    constexpr int JF = TNN/16;            // B col-frags per warp
    constexpr int JH = JF/2;
    constexpr int STAGE = 8192 + TNN*128; // A hi/lo 8K + B hi/lo
    constexpr int BCOPY = TNN*4;
    __shared__ __align__(128) char dsm[4*STAGE];
    uint32_t sbase = smem_to_u32(dsm);

    const int tid = threadIdx.x;
    const int wid = tid >> 5;
    const int lane = tid & 31;
    const int m0 = blockIdx.y * TM;
    const int n0 = blockIdx.x * TNN;
    const int wm = (wid >> 1) * 32;
    const int wn = (wid & 1) * (TNN/2);

    const int qm = lane >> 3, rr = lane & 7;
    const int lrow = (qm & 1)*8 + rr;
    const int lkof = (qm >> 1)*8;

    float acc[2][JF][4];
    #pragma unroll
    for (int i = 0; i < 2; ++i)
        #pragma unroll
        for (int j = 0; j < JF; ++j)
            #pragma unroll
            for (int s = 0; s < 4; ++s) acc[i][j][s] = 0.f;

    const int nst1 = Kpad >> 5;
    const bool do2 = (A2h != nullptr) && (n0 < n2_limit);
    const int nst = do2 ? 2*nst1 : nst1;

    auto stage = [&](int t) {
        int pass = (t >= nst1) ? 1 : 0;
        int k0 = (t - pass*nst1) << 5;
        const unsigned short* pAh = pass ? A2h : Ah;
        const unsigned short* pAl = pass ? A2l : Al;
        const unsigned short* pBh = pass ? B2h : Bh;
        const unsigned short* pBl = pass ? B2l : Bl;
        int la = pass ? lda2 : lda;
        int lb = pass ? ldb2 : ldb;
        int bm = pass ? b2mask : NOMASK;
        uint32_t sb = sbase + (t & 3) * STAGE;
        #pragma unroll
        for (int qq = 0; qq*128 < 512 + 2*BCOPY; ++qq) {
            int c = tid + (qq << 7);
            if (c < 512) {             // A: hi [0,256) lo [256,512)
                int part = c >> 8;
                int sub = c & 255;
                int row = sub >> 2, quad = sub & 3;
                int gr = m0 + row;
                bool ok = gr < M;
                const unsigned short* s = (part ? pAl : pAh)
                                          + (size_t)(ok ? gr : 0)*la + k0 + quad*8;
                uint32_t off = sw64((uint32_t)(row*64 + quad*16));
                cpasync16(sb + part*4096 + off, s, ok);
            } else {                   // B: hi then lo, BCOPY each
                int cb = c - 512;
                int part = (cb >= BCOPY) ? 1 : 0;
                int sub = cb - part*BCOPY;
                int row = sub >> 2, quad = sub & 3;
                int gn = n0 + row;
                bool ok = gn < N;
                int er = (ok ? gn : 0) & bm;
                const unsigned short* s = (part ? pBl : pBh)
                                          + (size_t)er*lb + k0 + quad*8;
                uint32_t off = sw64((uint32_t)(row*64 + quad*16));
                cpasync16(sb + 8192 + part*(TNN*64) + off, s, ok);
            }
        }
        cp_commit();
    };

    stage(0);
    if (nst > 1) stage(1);
    if (nst > 2) stage(2);
    for (int t = 0; t < nst; ++t) {
        if (t + 2 < nst) cp_waitN<2>();
        else if (t + 1 < nst) cp_waitN<1>();
        else cp_waitN<0>();
        __syncthreads();
        uint32_t sb = sbase + (t & 3) * STAGE;
        uint32_t sa_hi = sb, sa_lo = sb + 4096;
        uint32_t sb_hi = sb + 8192, sb_lo = sb + 8192 + TNN*64;
        #pragma unroll
        for (int k0 = 0; k0 < 32; k0 += 16) {
            uint32_t ah[2][4], al[2][4], bh[JF][2], bl[JF][2];
            #pragma unroll
            for (int i = 0; i < 2; ++i) {
                uint32_t off = sw64((uint32_t)((wm + i*16 + lrow)*64 + (k0 + lkof)*2));
                ldsm_x4(ah[i], sa_hi + off);
                ldsm_x4(al[i], sa_lo + off);
            }
            #pragma unroll
            for (int jh = 0; jh < JH; ++jh) {
                uint32_t off = sw64((uint32_t)((wn + jh*16 + lrow)*64 + (k0 + lkof)*2));
                uint32_t r[4];
                ldsm_x4(r, sb_hi + off);
                bh[2*jh][0]=r[0]; bh[2*jh][1]=r[2]; bh[2*jh+1][0]=r[1]; bh[2*jh+1][1]=r[3];
                ldsm_x4(r, sb_lo + off);
                bl[2*jh][0]=r[0]; bl[2*jh][1]=r[2]; bl[2*jh+1][0]=r[1]; bl[2*jh+1][1]=r[3];
            }
            #pragma unroll
            for (int i = 0; i < 2; ++i)
                #pragma unroll
                for (int j = 0; j < JF; ++j) {
                    mma16816(acc[i][j], ah[i], bh[j]);
                    mma16816(acc[i][j], ah[i], bl[j]);
                    mma16816(acc[i][j], al[i], bh[j]);
                }
        }
        if (t + 3 < nst) stage(t + 3);
    }

    // epilogue
    const int g = lane >> 2, tq = (lane & 3)*2;
    #pragma unroll
    for (int i = 0; i < 2; ++i) {
        #pragma unroll
        for (int half = 0; half < 2; ++half) {
            int m = m0 + wm + i*16 + g + half*8;
            if (m >= M) continue;
            #pragma unroll
            for (int j = 0; j < JF; ++j) {
                #pragma unroll
                for (int s = 0; s < 2; ++s) {
                    int n = n0 + wn + j*8 + tq + s;
                    if (n >= N) continue;
                    float x = acc[i][j][half*2 + s];
                    if (MODE == MODE_NONE) {
                        C[(size_t)m*ldc + n] = x;
                    } else if (MODE == MODE_ZRH) {
                        x += bias[n];
                        if (n < CD) {
                            p0[m*CD + n] = 1.f/(1.f + expf(-x));
                        } else if (n < 2*CD) {
                            int nn = n - CD;
                            float rn = (1.f/(1.f + expf(-x))) * p2[m*CD + nn];
                            split_bf(rn, &q0[m*CD + nn], &q1[m*CD + nn]);
                        } else {
                            p1[m*CD + (n - 2*CD)] = x;
                        }
                    } else if (MODE == MODE_GRU2) {
                        float hc = tanhf(x + p1[m*CD + n]);
                        float z  = p0[m*CD + n];
                        float nv = (1.f - z)*p2[m*CD + n] + z*hc;
                        p2[m*CD + n] = nv;
                        split_bf(nv, &q0[m*CD + n], &q1[m*CD + n]);
                    } else { // MODE_TANH
                        C[(size_t)m*ldc + n] = tanhf(x + bias[n]);
                    }
                }
            }
        }
    }
}

// ---------------- semantic-branch kernels ----------------
// two n-rows per block: one d_fwd stream feeds two accumulations (halves L2 traffic)
__global__ __launch_bounds__(256) void k_coeff(const float* __restrict__ fcab) {
    int n0 = blockIdx.x * 2;
    int warp = threadIdx.x >> 5, lane = threadIdx.x & 31;
    float fw0[32], fw1[32], v_r[32];
    const float* r0 = d_fwh + n0*CD + lane;
    #pragma unroll
    for (int q = 0; q < 32; ++q) {
        fw0[q] = r0[q*32];
        fw1[q] = r0[CD + q*32];
        v_r[q] = d_v[q*32 + lane];
    }
    float c0 = 0.f;
    #pragma unroll
    for (int q = 0; q < 32; ++q) c0 += d_c0p[q*32 + lane];
    #pragma unroll
    for (int o = 16; o > 0; o >>= 1) c0 += __shfl_xor_sync(0xffffffffu, c0, o);
    c0 += fcab[0];
    for (int l = warp; l < LD; l += 8) {
        const float* fw = d_fwd + l*CD + lane;
        float a0 = 0.f, a1 = 0.f;
        #pragma unroll
        for (int q = 0; q < 32; ++q) {
            float w = fw[q*32];
            float t0, t1;
            float px = fw0[q] * w, py = fw1[q] * w;
            asm("tanh.approx.f32 %0, %1;" : "=f"(t0) : "f"(px));
            asm("tanh.approx.f32 %0, %1;" : "=f"(t1) : "f"(py));
            a0 += t0 * v_r[q];
            a1 += t1 * v_r[q];
        }
        #pragma unroll
        for (int o = 16; o > 0; o >>= 1) {
            a0 += __shfl_xor_sync(0xffffffffu, a0, o);
            a1 += __shfl_xor_sync(0xffffffffu, a1, o);
        }
        if (lane == 0) {
            d_coeff[n0*LD + l]     = a0 + c0;
            d_coeff[(n0+1)*LD + l] = a1 + c0;
        }
    }
}

__global__ __launch_bounds__(256) void k_softmax() {
    int g = blockIdx.x*8 + (threadIdx.x >> 5);
    int lane = threadIdx.x & 31;
    if (g >= NP*LD/HW) return;
    float* p = d_coeff + g*HW;
    float vals[7];
    float mx = -1e30f;
    #pragma unroll
    for (int q = 0; q < 7; ++q) {
        int i = lane + q*32;
        vals[q] = (i < HW) ? p[i] : -1e30f;
        mx = fmaxf(mx, vals[q]);
    }
    #pragma unroll
    for (int o = 16; o > 0; o >>= 1) mx = fmaxf(mx, __shfl_xor_sync(0xffffffffu, mx, o));
    float s = 0.f;
    #pragma unroll
    for (int q = 0; q < 7; ++q) {
        int i = lane + q*32;
        if (i < HW) { vals[q] = expf(vals[q] - mx); s += vals[q]; }
    }
    #pragma unroll
    for (int o = 16; o > 0; o >>= 1) s += __shfl_xor_sync(0xffffffffu, s, o);
    float inv = 1.f / s;
    #pragma unroll
    for (int q = 0; q < 7; ++q) {
        int i = lane + q*32;
        if (i < HW) p[i] = vals[q]*inv;
    }
}

__global__ __launch_bounds__(256) void k_g(const float* __restrict__ img) {
    __shared__ float s[HW];
    int b = blockIdx.x / LD, l = blockIdx.x % LD;
    for (int tt = threadIdx.x; tt < HW; tt += 256)
        s[tt] = d_coeff[(b*HW + tt)*LD + l];
    __syncthreads();
    const float* xb = img + b*HW*CD;
    int c = threadIdx.x;
    float a0 = 0.f, a1 = 0.f, a2 = 0.f, a3 = 0.f;
    #pragma unroll 4
    for (int tt = 0; tt < HW; ++tt) {
        float w = s[tt];
        const float* xr = xb + tt*CD;
        a0 += w*xr[c]; a1 += w*xr[c+256]; a2 += w*xr[c+512]; a3 += w*xr[c+768];
    }
    int base = (b*LD + l)*CD + c;
    float vals[4] = {a0, a1, a2, a3};
    #pragma unroll
    for (int q = 0; q < 4; ++q) {
        int idx = base + q*256;
        d_nodes[idx] = vals[q];
        split_bf(vals[q], &c_g_h[idx], &c_g_l[idx]);
        c_nodes_h[idx] = c_g_h[idx];
        c_nodes_l[idx] = c_g_l[idx];
    }
}

__global__ __launch_bounds__(256) void k_a(const float* __restrict__ adj) {
    __shared__ float ar[LD];
    int b = blockIdx.x / LD, nn = blockIdx.x % LD;
    if (threadIdx.x < LD) ar[threadIdx.x] = adj[nn*LD + threadIdx.x];
    __syncthreads();
    int c = threadIdx.x;
    const float* nb = d_nodes + b*LD*CD;
    float a0 = 0.f, a1 = 0.f, a2 = 0.f, a3 = 0.f;
    #pragma unroll 4
    for (int m = 0; m < LD; ++m) {
        float w = ar[m];
        const float* nr = nb + m*CD;
        a0 += w*nr[c]; a1 += w*nr[c+256]; a2 += w*nr[c+512]; a3 += w*nr[c+768];
    }
    int base = (b*LD + nn)*CD + c;
    float vals[4] = {a0, a1, a2, a3};
    #pragma unroll
    for (int q = 0; q < 4; ++q) {
        int idx = base + q*256;
        split_bf(vals[q], &c_a_h[idx], &c_a_l[idx]);
    }
}

// ---------------- host ----------------
struct Sym {
    float *fwd, *v, *c0p, *ball, *fwh, *coeff, *nodes, *zbuf, *hbuf;
    unsigned short *imgh, *imgl, *fc1h, *fc1l, *wembh, *wembl, *fc2h, *fc2l;
    unsigned short *wallh, *walll, *u3h, *u3l, *u5h, *u5l, *fcoh, *fcol;
    unsigned short *ndh, *ndl, *ah, *al, *rnh, *rnl, *gh, *gl;
};
static void get_syms(Sym& S) {
    cudaGetSymbolAddress((void**)&S.fwd, d_fwd);
    cudaGetSymbolAddress((void**)&S.v, d_v);
    cudaGetSymbolAddress((void**)&S.c0p, d_c0p);
    cudaGetSymbolAddress((void**)&S.ball, d_ball);
    cudaGetSymbolAddress((void**)&S.fwh, d_fwh);
    cudaGetSymbolAddress((void**)&S.coeff, d_coeff);
    cudaGetSymbolAddress((void**)&S.nodes, d_nodes);
    cudaGetSymbolAddress((void**)&S.zbuf, d_zbuf);
    cudaGetSymbolAddress((void**)&S.hbuf, d_hbuf);
    cudaGetSymbolAddress((void**)&S.imgh, c_img_h);   cudaGetSymbolAddress((void**)&S.imgl, c_img_l);
    cudaGetSymbolAddress((void**)&S.fc1h, c_fc1_h);   cudaGetSymbolAddress((void**)&S.fc1l, c_fc1_l);
    cudaGetSymbolAddress((void**)&S.wembh, c_wemb_h); cudaGetSymbolAddress((void**)&S.wembl, c_wemb_l);
    cudaGetSymbolAddress((void**)&S.fc2h, c_fc2_h);   cudaGetSymbolAddress((void**)&S.fc2l, c_fc2_l);
    cudaGetSymbolAddress((void**)&S.wallh, c_wall_h); cudaGetSymbolAddress((void**)&S.walll, c_wall_l);
    cudaGetSymbolAddress((void**)&S.u3h, c_u3_h);     cudaGetSymbolAddress((void**)&S.u3l, c_u3_l);
    cudaGetSymbolAddress((void**)&S.u5h, c_u5_h);     cudaGetSymbolAddress((void**)&S.u5l, c_u5_l);
    cudaGetSymbolAddress((void**)&S.fcoh, c_fco_h);   cudaGetSymbolAddress((void**)&S.fcol, c_fco_l);
    cudaGetSymbolAddress((void**)&S.ndh, c_nodes_h);  cudaGetSymbolAddress((void**)&S.ndl, c_nodes_l);
    cudaGetSymbolAddress((void**)&S.ah, c_a_h);       cudaGetSymbolAddress((void**)&S.al, c_a_l);
    cudaGetSymbolAddress((void**)&S.rnh, c_rn_h);     cudaGetSymbolAddress((void**)&S.rnl, c_rn_l);
    cudaGetSymbolAddress((void**)&S.gh, c_g_h);       cudaGetSymbolAddress((void**)&S.gl, c_g_l);
}

template<int MODE, int TNN>
static void tg(const unsigned short* Ah, const unsigned short* Al, int lda,
               const unsigned short* Bh, const unsigned short* Bl, int ldb,
               const unsigned short* A2h, const unsigned short* A2l, int lda2,
               const unsigned short* B2h, const unsigned short* B2l, int ldb2,
               int b2mask, int n2lim, int M, int N, int Kpad,
               const float* bias, float* p0, float* p1, float* p2,
               unsigned short* q0, unsigned short* q1, float* C, int ldc) {
    dim3 grid((N + TNN - 1)/TNN, (M + TM - 1)/TM);
    t_gemm<MODE, TNN><<<grid, 128>>>(Ah, Al, lda, Bh, Bl, ldb, A2h, A2l, lda2,
                                     B2h, B2l, ldb2, b2mask, n2lim, M, N, Kpad,
                                     bias, p0, p1, p2, q0, q1, C, ldc);
}

extern "C" void kernel_launch(void* const* d_in, const int* in_sizes, int n_in,
                              void* d_out, int out_size) {
    const float* img  = (const float*)d_in[0];
    const float* wemb = (const float*)d_in[1];
    const float* adj  = (const float*)d_in[2];
    const float* fc1  = (const float*)d_in[3];
    const float* fc2  = (const float*)d_in[4];
    const float* fc3  = (const float*)d_in[5];
    const float* fc3b = (const float*)d_in[6];
    const float* fca  = (const float*)d_in[7];
    const float* fcab = (const float*)d_in[8];
    const float* w3   = (const float*)d_in[9];
    const float* b3   = (const float*)d_in[10];
    const float* u3   = (const float*)d_in[11];
    const float* u3b  = (const float*)d_in[12];
    const float* w4   = (const float*)d_in[13];
    const float* b4   = (const float*)d_in[14];
    const float* w5   = (const float*)d_in[15];
    const float* b5   = (const float*)d_in[16];
    const float* u5   = (const float*)d_in[17];
    const float* u5b  = (const float*)d_in[18];
    const float* fco  = (const float*)d_in[19];
    const float* fcob = (const float*)d_in[20];
    float* out = (float*)d_out;

    Sym S; get_syms(S);

    // 1-2: operand prep (A: semantic, B: GGNN)
    k_prepA<<<1024, 256>>>(fc1, img, wemb, fc2);
    k_prepB<<<2048, 256>>>(u3, u5, fco, w3, w4, w5, b3, u3b, b4, b5, u5b,
                           fc3, fca, fc3b);
    // 3: f_wd = wemb @ fc2^T
    tg<MODE_NONE, 32>(S.wembh, S.wembl, WPAD, S.fc2h, S.fc2l, WPAD,
                      nullptr, nullptr, 0, nullptr, nullptr, 0, NOMASK, 0,
                      LD, CD, WPAD, nullptr, nullptr, nullptr, nullptr, nullptr, nullptr,
                      S.fwd, CD);
    // 4: f_wh = x @ fc1^T   (ncu capture slot)
    tg<MODE_NONE, 32>(S.imgh, S.imgl, CD, S.fc1h, S.fc1l, CD,
                      nullptr, nullptr, 0, nullptr, nullptr, 0, NOMASK, 0,
                      NP, CD, CD, nullptr, nullptr, nullptr, nullptr, nullptr, nullptr,
                      S.fwh, CD);
    // 5-7: semantic chain
    k_coeff<<<NP/2, 256>>>(fcab);
    k_softmax<<<40, 256>>>();
    k_g<<<BT*LD, 256>>>(img);

    // GGNN
    for (int step = 0; step < 3; ++step) {
        k_a<<<BT*LD, 256>>>(adj);
        tg<MODE_ZRH, 32>(S.ah, S.al, CD, S.wallh, S.walll, CD,
                         S.ndh, S.ndl, CD, S.u3h, S.u3l, CD, CD-1, 2*CD,
                         NR, 3*CD, CD, S.ball, S.zbuf, S.hbuf, S.nodes,
                         S.rnh, S.rnl, nullptr, 0);
        tg<MODE_GRU2, 32>(S.rnh, S.rnl, CD, S.u5h, S.u5l, CD,
                          nullptr, nullptr, 0, nullptr, nullptr, 0, NOMASK, 0,
                          NR, CD, CD, nullptr, S.zbuf, S.hbuf, S.nodes,
                          S.ndh, S.ndl, nullptr, 0);
    }

    // out = tanh([nodes, g] @ fco^T + fco_b): dual-K over fco column halves
    tg<MODE_TANH, 32>(S.ndh, S.ndl, CD, S.fcoh, S.fcol, 2*CD,
                      S.gh, S.gl, CD, S.fcoh + CD, S.fcol + CD, 2*CD, NOMASK, NOMASK,
                      NR, OD, CD, fcob, nullptr, nullptr, nullptr, nullptr, nullptr,
                      out, OD);
}

// round 13
// speedup vs baseline: 2.8507x; 1.0177x over previous
#include <cuda_runtime.h>
#include <cuda_bf16.h>
#include <math.h>
#include <stdint.h>

#define CD 1024
#define LD 80
#define WDIM 300
#define WPAD 320
#define HW 196
#define BT 4
#define NP 784
#define OD 2048
#define NR (BT*LD)
#define NE (NR*CD)

#define MODE_NONE 0
#define MODE_ZRH  1
#define MODE_GRU2 2
#define MODE_TANH 3

#define TM 64
#define NOMASK 0x7FFFFFFF

// ---------------- fp32 scratch ----------------
__device__ float d_fwd[LD*CD];
__device__ float d_v[CD];
__device__ float d_c0p[CD];
__device__ float d_ball[3*CD];
__device__ float d_fwh[NP*CD];
__device__ float d_coeff[NP*LD];
__device__ float d_nodes[NE];
__device__ float d_zbuf[NE];
__device__ float d_hbuf[NE];

// ---------------- bf16 hi/lo operand buffers ----------------
__device__ unsigned short c_img_h[NP*CD],    c_img_l[NP*CD];
__device__ unsigned short c_fc1_h[CD*CD],    c_fc1_l[CD*CD];
__device__ unsigned short c_wemb_h[LD*WPAD], c_wemb_l[LD*WPAD];
__device__ unsigned short c_fc2_h[CD*WPAD],  c_fc2_l[CD*WPAD];
__device__ unsigned short c_wall_h[3*CD*CD], c_wall_l[3*CD*CD];
__device__ unsigned short c_u3_h[CD*CD],     c_u3_l[CD*CD];
__device__ unsigned short c_u5_h[CD*CD],     c_u5_l[CD*CD];
__device__ unsigned short c_fco_h[OD*2*CD],  c_fco_l[OD*2*CD];
__device__ unsigned short c_nodes_h[NE],     c_nodes_l[NE];
__device__ unsigned short c_a_h[NE],         c_a_l[NE];
__device__ unsigned short c_rn_h[NE],        c_rn_l[NE];
__device__ unsigned short c_g_h[NE],         c_g_l[NE];

// ---------------- helpers ----------------
__device__ __forceinline__ uint32_t smem_to_u32(const void* p) {
    uint32_t a;
    asm("{ .reg .u64 t; cvta.to.shared.u64 t, %1; cvt.u32.u64 %0, t; }" : "=r"(a) : "l"(p));
    return a;
}
__device__ __forceinline__ float tanha(float x) {
    float t;
    asm("tanh.approx.f32 %0, %1;" : "=f"(t) : "f"(x));
    return t;
}
__device__ __forceinline__ float sigf(float x) {
    return __fdividef(1.f, 1.f + __expf(-x));
}
__device__ __forceinline__ void split_bf(float v, unsigned short* h, unsigned short* l) {
    __nv_bfloat16 hb = __float2bfloat16(v);
    *h = __bfloat16_as_ushort(hb);
    *l = __bfloat16_as_ushort(__float2bfloat16(v - __bfloat162float(hb)));
}
// quad split: 4 elements -> uint2 hi + uint2 lo
__device__ __forceinline__ void split4(float4 v,
                                       unsigned short* hbase, unsigned short* lbase, int e) {
    __nv_bfloat16 h0 = __float2bfloat16(v.x), h1 = __float2bfloat16(v.y);
    __nv_bfloat16 h2 = __float2bfloat16(v.z), h3 = __float2bfloat16(v.w);
    float l0 = v.x - __bfloat162float(h0), l1 = v.y - __bfloat162float(h1);
    float l2 = v.z - __bfloat162float(h2), l3 = v.w - __bfloat162float(h3);
    uint2 hp, lp;
    hp.x = (uint32_t)__bfloat16_as_ushort(h0) | ((uint32_t)__bfloat16_as_ushort(h1) << 16);
    hp.y = (uint32_t)__bfloat16_as_ushort(h2) | ((uint32_t)__bfloat16_as_ushort(h3) << 16);
    lp.x = (uint32_t)__bfloat16_as_ushort(__float2bfloat16(l0)) |
           ((uint32_t)__bfloat16_as_ushort(__float2bfloat16(l1)) << 16);
    lp.y = (uint32_t)__bfloat16_as_ushort(__float2bfloat16(l2)) |
           ((uint32_t)__bfloat16_as_ushort(__float2bfloat16(l3)) << 16);
    *(uint2*)&hbase[e] = hp;
    *(uint2*)&lbase[e] = lp;
}
__device__ __forceinline__ void ldsm_x4(uint32_t* r, uint32_t addr) {
    asm volatile("ldmatrix.sync.aligned.m8n8.x4.shared.b16 {%0,%1,%2,%3}, [%4];"
        : "=r"(r[0]), "=r"(r[1]), "=r"(r[2]), "=r"(r[3]) : "r"(addr));
}
__device__ __forceinline__ void mma16816(float* c, const uint32_t* a, const uint32_t* b) {
    asm volatile("mma.sync.aligned.m16n8k16.row.col.f32.bf16.bf16.f32 "
        "{%0,%1,%2,%3}, {%4,%5,%6,%7}, {%8,%9}, {%0,%1,%2,%3};"
        : "+f"(c[0]), "+f"(c[1]), "+f"(c[2]), "+f"(c[3])
        : "r"(a[0]), "r"(a[1]), "r"(a[2]), "r"(a[3]), "r"(b[0]), "r"(b[1]));
}
__device__ __forceinline__ void cpasync16(uint32_t dst, const void* src, bool ok) {
    asm volatile("cp.async.cg.shared.global [%0], [%1], 16, %2;"
        :: "r"(dst), "l"(src), "r"(ok ? 16 : 0) : "memory");
}
__device__ __forceinline__ void cp_commit() {
    asm volatile("cp.async.commit_group;" ::: "memory");
}
template<int N> __device__ __forceinline__ void cp_waitN() {
    asm volatile("cp.async.wait_group %0;" :: "n"(N) : "memory");
}
__device__ __forceinline__ uint32_t sw64(uint32_t off) {
    return off ^ ((off >> 3) & 0x30);
}

// ---------------- merged prep: all converts (float4) + wsum + bias + v + c0 ----------
__global__ void k_prep(const float* __restrict__ fc1, const float* __restrict__ img,
                       const float* __restrict__ wemb, const float* __restrict__ fc2,
                       const float* __restrict__ u3, const float* __restrict__ u5,
                       const float* __restrict__ fco,
                       const float* __restrict__ w3, const float* __restrict__ w4,
                       const float* __restrict__ w5,
                       const float* __restrict__ b3, const float* __restrict__ u3b,
                       const float* __restrict__ b4, const float* __restrict__ b5,
                       const float* __restrict__ u5b,
                       const float* __restrict__ fc3, const float* __restrict__ fca,
                       const float* __restrict__ fc3b) {
    const int q1 = CD*CD/4;                 // fc1
    const int q2 = q1 + NP*CD/4;            // img
    const int q3 = q2 + LD*WPAD/4;          // wemb (padded)
    const int q4 = q3 + CD*WPAD/4;          // fc2  (padded)
    const int q5 = q4 + CD*CD/4;            // u3
    const int q6 = q5 + CD*CD/4;            // u5
    const int q7 = q6 + OD*2*CD/4;          // fco
    const int q8 = q7 + 3*CD*CD/4;          // wall summed
    const int q9 = q8 + 3*CD;               // bias
    const int q10 = q9 + CD;                // v
    const int q11 = q10 + CD;               // c0 partials
    int stride = gridDim.x*blockDim.x;
    for (int i = blockIdx.x*blockDim.x + threadIdx.x; i < q11; i += stride) {
        if (i < q1) {
            int e = 4*i;
            split4(*(const float4*)&fc1[e], c_fc1_h, c_fc1_l, e);
        } else if (i < q2) {
            int e = 4*(i - q1);
            split4(*(const float4*)&img[e], c_img_h, c_img_l, e);
        } else if (i < q3) {
            int e = 4*(i - q2);
            int r = e / WPAD, c = e - r*WPAD;
            float4 v = (c < WDIM) ? *(const float4*)&wemb[r*WDIM + c]
                                  : make_float4(0.f, 0.f, 0.f, 0.f);
            split4(v, c_wemb_h, c_wemb_l, e);
        } else if (i < q4) {
            int e = 4*(i - q3);
            int r = e / WPAD, c = e - r*WPAD;
            float4 v = (c < WDIM) ? *(const float4*)&fc2[r*WDIM + c]
                                  : make_float4(0.f, 0.f, 0.f, 0.f);
            split4(v, c_fc2_h, c_fc2_l, e);
        } else if (i < q5) {
            int e = 4*(i - q4);
            split4(*(const float4*)&u3[e], c_u3_h, c_u3_l, e);
        } else if (i < q6) {
            int e = 4*(i - q5);
            split4(*(const float4*)&u5[e], c_u5_h, c_u5_l, e);
        } else if (i < q7) {
            int e = 4*(i - q6);
            split4(*(const float4*)&fco[e], c_fco_h, c_fco_l, e);
        } else if (i < q8) {
            int e = 4*(i - q7);
            int which = e / (CD*CD);
            int rem = e - which*(CD*CD);
            int r = rem >> 10, c = rem & (CD-1);
            const float* w = (which==0) ? w3 : (which==1) ? w4 : w5;
            float4 a = *(const float4*)&w[r*2*CD + c];
            float4 b = *(const float4*)&w[r*2*CD + CD + c];
            split4(make_float4(a.x+b.x, a.y+b.y, a.z+b.z, a.w+b.w),
                   c_wall_h, c_wall_l, e);
        } else if (i < q9) {
            int j = i - q8;
            int which = j >> 10, c = j & (CD-1);
            if (which == 0)      d_ball[c]        = b3[c] + u3b[c];
            else if (which == 1) d_ball[CD + c]   = b4[c] + u3b[c]; // torch bug kept
            else                 d_ball[2*CD + c] = b5[c] + u5b[c];
        } else if (i < q10) {
            int c = i - q9;                 // v[c] = sum_j fca[j]*fc3[j,c]
            float acc = 0.f;
            #pragma unroll 8
            for (int j = 0; j < CD; ++j) acc += fca[j] * fc3[j*CD + c];
            d_v[c] = acc;
        } else {
            int j = i - q10;                // c0 partial
            d_c0p[j] = fc3b[j] * fca[j];
        }
    }
}

// ---------------- tensor GEMM: 4-stage cp.async ring, ONE barrier per stage ----------
// C = epi( A@B^T [+ A2@B2^T] + bias ); fp32 via bf16 split (hh + hl + lh).
template<int MODE, int TNN>
__global__ __launch_bounds__(128) void t_gemm(
    const unsigned short* __restrict__ Ah, const unsigned short* __restrict__ Al, int lda,
    const unsigned short* __restrict__ Bh, const unsigned short* __restrict__ Bl, int ldb,
    const unsigned short* __restrict__ A2h, const unsigned short* __restrict__ A2l, int lda2,
    const unsigned short* __restrict__ B2h, const unsigned short* __restrict__ B2l, int ldb2,
    int b2mask, int n2_limit,
    int M, int N, int Kpad,
    const float* __restrict__ bias,
    float* __restrict__ p0, float* __restrict__ p1, float* __restrict__ p2,
    unsigned short* __restrict__ q0, unsigned short* __restrict__ q1,
    float* __restrict__ C, int ldc)
{
    constexpr int JF = TNN/16;
    constexpr int JH = JF/2;
    constexpr int STAGE = 8192 + TNN*128;
    constexpr int BCOPY = TNN*4;
    __shared__ __align__(128) char dsm[4*STAGE];
    uint32_t sbase = smem_to_u32(dsm);

    const int tid = threadIdx.x;
    const int wid = tid >> 5;
    const int lane = tid & 31;
    const int m0 = blockIdx.y * TM;
    const int n0 = blockIdx.x * TNN;
    const int wm = (wid >> 1) * 32;
    const int wn = (wid & 1) * (TNN/2);

    const int qm = lane >> 3, rr = lane & 7;
    const int lrow = (qm & 1)*8 + rr;
    const int lkof = (qm >> 1)*8;

    float acc[2][JF][4];
    #pragma unroll
    for (int i = 0; i < 2; ++i)
        #pragma unroll
        for (int j = 0; j < JF; ++j)
            #pragma unroll
            for (int s = 0; s < 4; ++s) acc[i][j][s] = 0.f;

    const int nst1 = Kpad >> 5;
    const bool do2 = (A2h != nullptr) && (n0 < n2_limit);
    const int nst = do2 ? 2*nst1 : nst1;

    auto stage = [&](int t) {
        int pass = (t >= nst1) ? 1 : 0;
        int k0 = (t - pass*nst1) << 5;
        const unsigned short* pAh = pass ? A2h : Ah;
        const unsigned short* pAl = pass ? A2l : Al;
        const unsigned short* pBh = pass ? B2h : Bh;
        const unsigned short* pBl = pass ? B2l : Bl;
        int la = pass ? lda2 : lda;
        int lb = pass ? ldb2 : ldb;
        int bm = pass ? b2mask : NOMASK;
        uint32_t sb = sbase + (t & 3) * STAGE;
        #pragma unroll
        for (int qq = 0; qq*128 < 512 + 2*BCOPY; ++qq) {
            int c = tid + (qq << 7);
            if (c < 512) {
                int part = c >> 8;
                int sub = c & 255;
                int row = sub >> 2, quad = sub & 3;
                int gr = m0 + row;
                bool ok = gr < M;
                const unsigned short* s = (part ? pAl : pAh)
                                          + (size_t)(ok ? gr : 0)*la + k0 + quad*8;
                uint32_t off = sw64((uint32_t)(row*64 + quad*16));
                cpasync16(sb + part*4096 + off, s, ok);
            } else {
                int cb = c - 512;
                int part = (cb >= BCOPY) ? 1 : 0;
                int sub = cb - part*BCOPY;
                int row = sub >> 2, quad = sub & 3;
                int gn = n0 + row;
                bool ok = gn < N;
                int er = (ok ? gn : 0) & bm;
                const unsigned short* s = (part ? pBl : pBh)
                                          + (size_t)er*lb + k0 + quad*8;
                uint32_t off = sw64((uint32_t)(row*64 + quad*16));
                cpasync16(sb + 8192 + part*(TNN*64) + off, s, ok);
            }
        }
        cp_commit();
    };

    stage(0);
    if (nst > 1) stage(1);
    if (nst > 2) stage(2);
    for (int t = 0; t < nst; ++t) {
        if (t + 2 < nst) cp_waitN<2>();
        else if (t + 1 < nst) cp_waitN<1>();
        else cp_waitN<0>();
        __syncthreads();
        uint32_t sb = sbase + (t & 3) * STAGE;
        uint32_t sa_hi = sb, sa_lo = sb + 4096;
        uint32_t sb_hi = sb + 8192, sb_lo = sb + 8192 + TNN*64;
        #pragma unroll
        for (int k0 = 0; k0 < 32; k0 += 16) {
            uint32_t ah[2][4], al[2][4], bh[JF][2], bl[JF][2];
            #pragma unroll
            for (int i = 0; i < 2; ++i) {
                uint32_t off = sw64((uint32_t)((wm + i*16 + lrow)*64 + (k0 + lkof)*2));
                ldsm_x4(ah[i], sa_hi + off);
                ldsm_x4(al[i], sa_lo + off);
            }
            #pragma unroll
            for (int jh = 0; jh < JH; ++jh) {
                uint32_t off = sw64((uint32_t)((wn + jh*16 + lrow)*64 + (k0 + lkof)*2));
                uint32_t r[4];
                ldsm_x4(r, sb_hi + off);
                bh[2*jh][0]=r[0]; bh[2*jh][1]=r[2]; bh[2*jh+1][0]=r[1]; bh[2*jh+1][1]=r[3];
                ldsm_x4(r, sb_lo + off);
                bl[2*jh][0]=r[0]; bl[2*jh][1]=r[2]; bl[2*jh+1][0]=r[1]; bl[2*jh+1][1]=r[3];
            }
            #pragma unroll
            for (int i = 0; i < 2; ++i)
                #pragma unroll
                for (int j = 0; j < JF; ++j) {
                    mma16816(acc[i][j], ah[i], bh[j]);
                    mma16816(acc[i][j], ah[i], bl[j]);
                    mma16816(acc[i][j], al[i], bh[j]);
                }
        }
        if (t + 3 < nst) stage(t + 3);
    }

    // epilogue (fast transcendentals: __expf / __fdividef / tanh.approx)
    const int g = lane >> 2, tq = (lane & 3)*2;
    #pragma unroll
    for (int i = 0; i < 2; ++i) {
        #pragma unroll
        for (int half = 0; half < 2; ++half) {
            int m = m0 + wm + i*16 + g + half*8;
            if (m >= M) continue;
            #pragma unroll
            for (int j = 0; j < JF; ++j) {
                #pragma unroll
                for (int s = 0; s < 2; ++s) {
                    int n = n0 + wn + j*8 + tq + s;
                    if (n >= N) continue;
                    float x = acc[i][j][half*2 + s];
                    if (MODE == MODE_NONE) {
                        C[(size_t)m*ldc + n] = x;
                    } else if (MODE == MODE_ZRH) {
                        x += bias[n];
                        if (n < CD) {
                            p0[m*CD + n] = sigf(x);
                        } else if (n < 2*CD) {
                            int nn = n - CD;
                            float rn = sigf(x) * p2[m*CD + nn];
                            split_bf(rn, &q0[m*CD + nn], &q1[m*CD + nn]);
                        } else {
                            p1[m*CD + (n - 2*CD)] = x;
                        }
                    } else if (MODE == MODE_GRU2) {
                        float hc = tanha(x + p1[m*CD + n]);
                        float z  = p0[m*CD + n];
                        float nv = (1.f - z)*p2[m*CD + n] + z*hc;
                        p2[m*CD + n] = nv;
                        split_bf(nv, &q0[m*CD + n], &q1[m*CD + n]);
                    } else { // MODE_TANH
                        C[(size_t)m*ldc + n] = tanha(x + bias[n]);
                    }
                }
            }
        }
    }
}

// ---------------- semantic-branch kernels ----------------
__global__ __launch_bounds__(256) void k_coeff(const float* __restrict__ fcab) {
    int n0 = blockIdx.x * 2;
    int warp = threadIdx.x >> 5, lane = threadIdx.x & 31;
    float fw0[32], fw1[32], v_r[32];
    const float* r0 = d_fwh + n0*CD + lane;
    #pragma unroll
    for (int q = 0; q < 32; ++q) {
        fw0[q] = r0[q*32];
        fw1[q] = r0[CD + q*32];
        v_r[q] = d_v[q*32 + lane];
    }
    float c0 = 0.f;
    #pragma unroll
    for (int q = 0; q < 32; ++q) c0 += d_c0p[q*32 + lane];
    #pragma unroll
    for (int o = 16; o > 0; o >>= 1) c0 += __shfl_xor_sync(0xffffffffu, c0, o);
    c0 += fcab[0];
    for (int l = warp; l < LD; l += 8) {
        const float* fw = d_fwd + l*CD + lane;
        float a0 = 0.f, a1 = 0.f;
        #pragma unroll
        for (int q = 0; q < 32; ++q) {
            float w = fw[q*32];
            float t0 = tanha(fw0[q] * w);
            float t1 = tanha(fw1[q] * w);
            a0 += t0 * v_r[q];
            a1 += t1 * v_r[q];
        }
        #pragma unroll
        for (int o = 16; o > 0; o >>= 1) {
            a0 += __shfl_xor_sync(0xffffffffu, a0, o);
            a1 += __shfl_xor_sync(0xffffffffu, a1, o);
        }
        if (lane == 0) {
            d_coeff[n0*LD + l]     = a0 + c0;
            d_coeff[(n0+1)*LD + l] = a1 + c0;
        }
    }
}

__global__ __launch_bounds__(256) void k_softmax() {
    int g = blockIdx.x*8 + (threadIdx.x >> 5);
    int lane = threadIdx.x & 31;
    if (g >= NP*LD/HW) return;
    float* p = d_coeff + g*HW;
    float vals[7];
    float mx = -1e30f;
    #pragma unroll
    for (int q = 0; q < 7; ++q) {
        int i = lane + q*32;
        vals[q] = (i < HW) ? p[i] : -1e30f;
        mx = fmaxf(mx, vals[q]);
    }
    #pragma unroll
    for (int o = 16; o > 0; o >>= 1) mx = fmaxf(mx, __shfl_xor_sync(0xffffffffu, mx, o));
    float s = 0.f;
    #pragma unroll
    for (int q = 0; q < 7; ++q) {
        int i = lane + q*32;
        if (i < HW) { vals[q] = __expf(vals[q] - mx); s += vals[q]; }
    }
    #pragma unroll
    for (int o = 16; o > 0; o >>= 1) s += __shfl_xor_sync(0xffffffffu, s, o);
    float inv = __fdividef(1.f, s);
    #pragma unroll
    for (int q = 0; q < 7; ++q) {
        int i = lane + q*32;
        if (i < HW) p[i] = vals[q]*inv;
    }
}

__global__ __launch_bounds__(256) void k_g(const float* __restrict__ img) {
    __shared__ float s[HW];
    int b = blockIdx.x / LD, l = blockIdx.x % LD;
    for (int tt = threadIdx.x; tt < HW; tt += 256)
        s[tt] = d_coeff[(b*HW + tt)*LD + l];
    __syncthreads();
    const float* xb = img + b*HW*CD;
    int c = threadIdx.x;
    float a0 = 0.f, a1 = 0.f, a2 = 0.f, a3 = 0.f;
    #pragma unroll 4
    for (int tt = 0; tt < HW; ++tt) {
        float w = s[tt];
        const float* xr = xb + tt*CD;
        a0 += w*xr[c]; a1 += w*xr[c+256]; a2 += w*xr[c+512]; a3 += w*xr[c+768];
    }
    int base = (b*LD + l)*CD + c;
    float vals[4] = {a0, a1, a2, a3};
    #pragma unroll
    for (int q = 0; q < 4; ++q) {
        int idx = base + q*256;
        d_nodes[idx] = vals[q];
        split_bf(vals[q], &c_g_h[idx], &c_g_l[idx]);
        c_nodes_h[idx] = c_g_h[idx];
        c_nodes_l[idx] = c_g_l[idx];
    }
}

__global__ __launch_bounds__(256) void k_a(const float* __restrict__ adj) {
    __shared__ float ar[LD];
    int b = blockIdx.x / LD, nn = blockIdx.x % LD;
    if (threadIdx.x < LD) ar[threadIdx.x] = adj[nn*LD + threadIdx.x];
    __syncthreads();
    int c = threadIdx.x;
    const float* nb = d_nodes + b*LD*CD;
    float a0 = 0.f, a1 = 0.f, a2 = 0.f, a3 = 0.f;
    #pragma unroll 4
    for (int m = 0; m < LD; ++m) {
        float w = ar[m];
        const float* nr = nb + m*CD;
        a0 += w*nr[c]; a1 += w*nr[c+256]; a2 += w*nr[c+512]; a3 += w*nr[c+768];
    }
    int base = (b*LD + nn)*CD + c;
    float vals[4] = {a0, a1, a2, a3};
    #pragma unroll
    for (int q = 0; q < 4; ++q) {
        int idx = base + q*256;
        split_bf(vals[q], &c_a_h[idx], &c_a_l[idx]);
    }
}

// ---------------- host ----------------
struct Sym {
    float *fwd, *v, *c0p, *ball, *fwh, *coeff, *nodes, *zbuf, *hbuf;
    unsigned short *imgh, *imgl, *fc1h, *fc1l, *wembh, *wembl, *fc2h, *fc2l;
    unsigned short *wallh, *walll, *u3h, *u3l, *u5h, *u5l, *fcoh, *fcol;
    unsigned short *ndh, *ndl, *ah, *al, *rnh, *rnl, *gh, *gl;
};
static void get_syms(Sym& S) {
    cudaGetSymbolAddress((void**)&S.fwd, d_fwd);
    cudaGetSymbolAddress((void**)&S.v, d_v);
    cudaGetSymbolAddress((void**)&S.c0p, d_c0p);
    cudaGetSymbolAddress((void**)&S.ball, d_ball);
    cudaGetSymbolAddress((void**)&S.fwh, d_fwh);
    cudaGetSymbolAddress((void**)&S.coeff, d_coeff);
    cudaGetSymbolAddress((void**)&S.nodes, d_nodes);
    cudaGetSymbolAddress((void**)&S.zbuf, d_zbuf);
    cudaGetSymbolAddress((void**)&S.hbuf, d_hbuf);
    cudaGetSymbolAddress((void**)&S.imgh, c_img_h);   cudaGetSymbolAddress((void**)&S.imgl, c_img_l);
    cudaGetSymbolAddress((void**)&S.fc1h, c_fc1_h);   cudaGetSymbolAddress((void**)&S.fc1l, c_fc1_l);
    cudaGetSymbolAddress((void**)&S.wembh, c_wemb_h); cudaGetSymbolAddress((void**)&S.wembl, c_wemb_l);
    cudaGetSymbolAddress((void**)&S.fc2h, c_fc2_h);   cudaGetSymbolAddress((void**)&S.fc2l, c_fc2_l);
    cudaGetSymbolAddress((void**)&S.wallh, c_wall_h); cudaGetSymbolAddress((void**)&S.walll, c_wall_l);
    cudaGetSymbolAddress((void**)&S.u3h, c_u3_h);     cudaGetSymbolAddress((void**)&S.u3l, c_u3_l);
    cudaGetSymbolAddress((void**)&S.u5h, c_u5_h);     cudaGetSymbolAddress((void**)&S.u5l, c_u5_l);
    cudaGetSymbolAddress((void**)&S.fcoh, c_fco_h);   cudaGetSymbolAddress((void**)&S.fcol, c_fco_l);
    cudaGetSymbolAddress((void**)&S.ndh, c_nodes_h);  cudaGetSymbolAddress((void**)&S.ndl, c_nodes_l);
    cudaGetSymbolAddress((void**)&S.ah, c_a_h);       cudaGetSymbolAddress((void**)&S.al, c_a_l);
    cudaGetSymbolAddress((void**)&S.rnh, c_rn_h);     cudaGetSymbolAddress((void**)&S.rnl, c_rn_l);
    cudaGetSymbolAddress((void**)&S.gh, c_g_h);       cudaGetSymbolAddress((void**)&S.gl, c_g_l);
}

template<int MODE, int TNN>
static void tg(const unsigned short* Ah, const unsigned short* Al, int lda,
               const unsigned short* Bh, const unsigned short* Bl, int ldb,
               const unsigned short* A2h, const unsigned short* A2l, int lda2,
               const unsigned short* B2h, const unsigned short* B2l, int ldb2,
               int b2mask, int n2lim, int M, int N, int Kpad,
               const float* bias, float* p0, float* p1, float* p2,
               unsigned short* q0, unsigned short* q1, float* C, int ldc) {
    dim3 grid((N + TNN - 1)/TNN, (M + TM - 1)/TM);
    t_gemm<MODE, TNN><<<grid, 128>>>(Ah, Al, lda, Bh, Bl, ldb, A2h, A2l, lda2,
                                     B2h, B2l, ldb2, b2mask, n2lim, M, N, Kpad,
                                     bias, p0, p1, p2, q0, q1, C, ldc);
}

extern "C" void kernel_launch(void* const* d_in, const int* in_sizes, int n_in,
                              void* d_out, int out_size) {
    const float* img  = (const float*)d_in[0];
    const float* wemb = (const float*)d_in[1];
    const float* adj  = (const float*)d_in[2];
    const float* fc1  = (const float*)d_in[3];
    const float* fc2  = (const float*)d_in[4];
    const float* fc3  = (const float*)d_in[5];
    const float* fc3b = (const float*)d_in[6];
    const float* fca  = (const float*)d_in[7];
    const float* fcab = (const float*)d_in[8];
    const float* w3   = (const float*)d_in[9];
    const float* b3   = (const float*)d_in[10];
    const float* u3   = (const float*)d_in[11];
    const float* u3b  = (const float*)d_in[12];
    const float* w4   = (const float*)d_in[13];
    const float* b4   = (const float*)d_in[14];
    const float* w5   = (const float*)d_in[15];
    const float* b5   = (const float*)d_in[16];
    const float* u5   = (const float*)d_in[17];
    const float* u5b  = (const float*)d_in[18];
    const float* fco  = (const float*)d_in[19];
    const float* fcob = (const float*)d_in[20];
    float* out = (float*)d_out;

    Sym S; get_syms(S);

    // 1: all prep
    k_prep<<<2048, 256>>>(fc1, img, wemb, fc2, u3, u5, fco,
                          w3, w4, w5, b3, u3b, b4, b5, u5b, fc3, fca, fc3b);
    // 2: padding launch keeps fwh at slot 4? no — 2: f_wd, 3: (small), 4: fwh? keep:
    // 2: f_wd = wemb @ fc2^T
    tg<MODE_NONE, 32>(S.wembh, S.wembl, WPAD, S.fc2h, S.fc2l, WPAD,
                      nullptr, nullptr, 0, nullptr, nullptr, 0, NOMASK, 0,
                      LD, CD, WPAD, nullptr, nullptr, nullptr, nullptr, nullptr, nullptr,
                      S.fwd, CD);
    // 3: k_softmax placeholder is wrong; keep simple order: 3 = fwh (capture slot moves to 3)
    // 4: f_wh = x @ fc1^T   — keep at slot 4 with a no-op-cheap launch before it? Instead:
    // keep original order: fwh at slot 4 via placing k_coeff dependency chain after.
    tg<MODE_NONE, 32>(S.imgh, S.imgl, CD, S.fc1h, S.fc1l, CD,
                      nullptr, nullptr, 0, nullptr, nullptr, 0, NOMASK, 0,
                      NP, CD, CD, nullptr, nullptr, nullptr, nullptr, nullptr, nullptr,
                      S.fwh, CD);
    // 4: k_coeff  (capture slot — the semantic hot kernel)
    k_coeff<<<NP/2, 256>>>(fcab);
    k_softmax<<<40, 256>>>();
    k_g<<<BT*LD, 256>>>(img);

    // GGNN
    for (int step = 0; step < 3; ++step) {
        k_a<<<BT*LD, 256>>>(adj);
        tg<MODE_ZRH, 32>(S.ah, S.al, CD, S.wallh, S.walll, CD,
                         S.ndh, S.ndl, CD, S.u3h, S.u3l, CD, CD-1, 2*CD,
                         NR, 3*CD, CD, S.ball, S.zbuf, S.hbuf, S.nodes,
                         S.rnh, S.rnl, nullptr, 0);
        tg<MODE_GRU2, 32>(S.rnh, S.rnl, CD, S.u5h, S.u5l, CD,
                          nullptr, nullptr, 0, nullptr, nullptr, 0, NOMASK, 0,
                          NR, CD, CD, nullptr, S.zbuf, S.hbuf, S.nodes,
                          S.ndh, S.ndl, nullptr, 0);
    }

    // out = tanh([nodes, g] @ fco^T + fco_b): dual-K over fco column halves
    tg<MODE_TANH, 32>(S.ndh, S.ndl, CD, S.fcoh, S.fcol, 2*CD,
                      S.gh, S.gl, CD, S.fcoh + CD, S.fcol + CD, 2*CD, NOMASK, NOMASK,
                      NR, OD, CD, fcob, nullptr, nullptr, nullptr, nullptr, nullptr,
                      out, OD);
}